// round 5
// baseline (speedup 1.0000x reference)
#include <cuda_runtime.h>
#include <cuda_fp16.h>
#include <cstdint>
#include <cstddef>

#define HID    1024
#define EMBED  512
#define BATCH  64
#define MAXLEN 1024
#define VOCAB  50257
#define NCHUNK 8            // 1024 attn dims / 128 per block

// ---------------- scratch (no allocations allowed) ----------------
__device__ float  g_dproj[BATCH * HID];
__device__ float  g_epart[NCHUNK * MAXLEN * BATCH];
__device__ float  g_alpha[MAXLEN * BATCH];
__device__ float  g_cpart[8 * BATCH * HID];
__device__ float  g_x[BATCH * (EMBED + HID)];
__device__ float  g_gi[BATCH * 3 * HID];
__device__ float  g_gh[BATCH * 3 * HID];
__device__ float  g_h0[BATCH * HID];
__device__ __half g_bh[HID * HID];                  // w1e^T fp16-hi [n][k]
__device__ __half g_bl[HID * HID];                  // w1e^T fp16-lo [n][k]
__device__ __half g_eh[(size_t)MAXLEN * BATCH * HID];   // enc fp16-hi
__device__ __half g_el[(size_t)MAXLEN * BATCH * HID];   // enc fp16-lo

// ---------------- prep: transpose + fp16-split w1e ----------------
__global__ void prep_b(const float* __restrict__ w1e) {
    __shared__ float tile[32][33];
    int k0 = blockIdx.x * 32, n0 = blockIdx.y * 32;
    int tx = threadIdx.x, ty = threadIdx.y;
    for (int i = ty; i < 32; i += 8)
        tile[i][tx] = w1e[(size_t)(k0 + i) * HID + n0 + tx];
    __syncthreads();
    for (int i = ty; i < 32; i += 8) {
        float v = tile[tx][i];
        __half hi = __float2half_rn(v);
        __half lo = __float2half_rn(v - __half2float(hi));
        g_bh[(size_t)(n0 + i) * HID + k0 + tx] = hi;
        g_bl[(size_t)(n0 + i) * HID + k0 + tx] = lo;
    }
}

// ---------------- prep: fp16-split enc_states ----------------
__global__ void prep_enc(const float* __restrict__ enc) {
    size_t i = ((size_t)blockIdx.x * 256 + threadIdx.x) * 4;
    float4 v = *(const float4*)(enc + i);
    __half h[4], l[4];
    float x[4] = {v.x, v.y, v.z, v.w};
    #pragma unroll
    for (int e = 0; e < 4; e++) {
        h[e] = __float2half_rn(x[e]);
        l[e] = __float2half_rn(x[e] - __half2float(h[e]));
    }
    *(uint2*)(g_eh + i) = *(uint2*)h;
    *(uint2*)(g_el + i) = *(uint2*)l;
}

// ---------------- helpers ----------------
__device__ __forceinline__ uint32_t smem_u32(const void* p) {
    uint32_t a;
    asm("{ .reg .u64 t; cvta.to.shared.u64 t, %1; cvt.u32.u64 %0, t; }" : "=r"(a) : "l"(p));
    return a;
}
__device__ __forceinline__ void cp16(void* s, const void* g) {
    asm volatile("cp.async.cg.shared.global [%0], [%1], 16;"
                 :: "r"(smem_u32(s)), "l"(g));
}
__device__ __forceinline__ void cp_commit() {
    asm volatile("cp.async.commit_group;" ::: "memory");
}
template <int N>
__device__ __forceinline__ void cp_wait() {
    asm volatile("cp.async.wait_group %0;" :: "n"(N) : "memory");
}
__device__ __forceinline__ void mma16816(float* d, const uint32_t* a, const uint32_t* b) {
    asm volatile("mma.sync.aligned.m16n8k16.row.col.f32.f16.f16.f32 "
                 "{%0,%1,%2,%3}, {%4,%5,%6,%7}, {%8,%9}, {%0,%1,%2,%3};"
                 : "+f"(d[0]), "+f"(d[1]), "+f"(d[2]), "+f"(d[3])
                 : "r"(a[0]), "r"(a[1]), "r"(a[2]), "r"(a[3]),
                   "r"(b[0]), "r"(b[1]));
}

// ---------------- attention GEMM: 512 thr, 16 warps, 3-stage cp.async ----------------
// block 128 rows x 128 attn dims, K=1024 in 32-chunks. warp tile 32x32.
// smem stride 40 halves (80B) => conflict-free fragment loads.
#define ASTRIDE 40
#define MATH 5120                     // halves per tile (128*40)
#define STAGE_BYTES 40960             // 4 tiles * 10240 B
#define NSTAGE 3
#define SMEM_TOTAL_ATT (NSTAGE * STAGE_BYTES)
#define KT 32

__global__ void __launch_bounds__(512, 1)
attn_mma(const float* __restrict__ w2) {
    extern __shared__ char smem[];
    const int bn = blockIdx.x;       // 0..7   n-chunk
    const int mt = blockIdx.y;       // 0..511 row tile
    const int tid = threadIdx.x;
    const int wid = tid >> 5, lane = tid & 31;
    const int wm = wid >> 2, wn = wid & 3;     // warps: 4(M) x 4(N)
    const int qr = lane >> 2, qc = lane & 3;

    const __half* gAh = g_eh + (size_t)mt * 128 * HID;
    const __half* gAl = g_el + (size_t)mt * 128 * HID;
    const __half* gBh = g_bh + (size_t)(bn * 128) * HID;
    const __half* gBl = g_bl + (size_t)(bn * 128) * HID;

    const int lr = tid >> 2, lc = tid & 3;     // loader: 128 rows x 4 chunks

    auto issue_load = [&](int kt) {
        char* base = smem + (kt % NSTAGE) * STAGE_BYTES;
        __half* sAh = (__half*)base;
        __half* sAl = sAh + MATH;
        __half* sBh = sAl + MATH;
        __half* sBl = sBh + MATH;
        size_t go = (size_t)lr * HID + kt * 32 + lc * 8;
        int so = lr * ASTRIDE + lc * 8;
        cp16(sAh + so, gAh + go);
        cp16(sAl + so, gAl + go);
        cp16(sBh + so, gBh + go);
        cp16(sBl + so, gBl + go);
        cp_commit();
    };

    float acc[2][4][4] = {};

    auto compute = [&](int kt) {
        const char* base = smem + (kt % NSTAGE) * STAGE_BYTES;
        const __half* sAh = (const __half*)base;
        const __half* sAl = sAh + MATH;
        const __half* sBh = sAl + MATH;
        const __half* sBl = sBh + MATH;
        #pragma unroll
        for (int ks = 0; ks < 32; ks += 16) {
            const int c0 = ks + qc * 2;
            uint32_t ah[2][4], al[2][4], bh[4][2], bl[4][2];
            #pragma unroll
            for (int m = 0; m < 2; m++) {
                const __half* p0 = sAh + (wm * 32 + m * 16 + qr) * ASTRIDE;
                const __half* p1 = sAl + (wm * 32 + m * 16 + qr) * ASTRIDE;
                ah[m][0] = *(const uint32_t*)(p0 + c0);
                ah[m][1] = *(const uint32_t*)(p0 + 8 * ASTRIDE + c0);
                ah[m][2] = *(const uint32_t*)(p0 + c0 + 8);
                ah[m][3] = *(const uint32_t*)(p0 + 8 * ASTRIDE + c0 + 8);
                al[m][0] = *(const uint32_t*)(p1 + c0);
                al[m][1] = *(const uint32_t*)(p1 + 8 * ASTRIDE + c0);
                al[m][2] = *(const uint32_t*)(p1 + c0 + 8);
                al[m][3] = *(const uint32_t*)(p1 + 8 * ASTRIDE + c0 + 8);
            }
            #pragma unroll
            for (int n = 0; n < 4; n++) {
                const __half* p0 = sBh + (wn * 32 + n * 8 + qr) * ASTRIDE;
                const __half* p1 = sBl + (wn * 32 + n * 8 + qr) * ASTRIDE;
                bh[n][0] = *(const uint32_t*)(p0 + c0);
                bh[n][1] = *(const uint32_t*)(p0 + c0 + 8);
                bl[n][0] = *(const uint32_t*)(p1 + c0);
                bl[n][1] = *(const uint32_t*)(p1 + c0 + 8);
            }
            #pragma unroll
            for (int m = 0; m < 2; m++)
                #pragma unroll
                for (int n = 0; n < 4; n++) mma16816(acc[m][n], ah[m], bh[n]);
            #pragma unroll
            for (int m = 0; m < 2; m++)
                #pragma unroll
                for (int n = 0; n < 4; n++) mma16816(acc[m][n], al[m], bh[n]);
            #pragma unroll
            for (int m = 0; m < 2; m++)
                #pragma unroll
                for (int n = 0; n < 4; n++) mma16816(acc[m][n], ah[m], bl[n]);
        }
    };

    issue_load(0);
    issue_load(1);
    for (int kt = 0; kt < KT; kt++) {
        cp_wait<1>();
        __syncthreads();
        if (kt + 2 < KT) issue_load(kt + 2);
        else cp_commit();                 // keep group count stable for wait<1>
        compute(kt);
    }

    // ---- epilogue: e_partial[row] = sum_n tanh(acc + dproj[b][n]) * w2[n] ----
    float rsum[2][2] = {};
    #pragma unroll
    for (int m = 0; m < 2; m++) {
        #pragma unroll
        for (int n = 0; n < 4; n++) {
            int ng0 = bn * 128 + wn * 32 + n * 8 + qc * 2;
            float w20 = w2[ng0], w21 = w2[ng0 + 1];
            #pragma unroll
            for (int pr = 0; pr < 2; pr++) {
                int row_local = wm * 32 + m * 16 + qr + pr * 8;
                int b = row_local & 63;
                const float* dp = g_dproj + (size_t)b * HID + ng0;
                rsum[m][pr] += tanhf(acc[m][n][pr * 2 + 0] + dp[0]) * w20
                             + tanhf(acc[m][n][pr * 2 + 1] + dp[1]) * w21;
            }
        }
    }
    #pragma unroll
    for (int m = 0; m < 2; m++)
        #pragma unroll
        for (int pr = 0; pr < 2; pr++) {
            float v = rsum[m][pr];
            v += __shfl_xor_sync(0xffffffffu, v, 1);
            v += __shfl_xor_sync(0xffffffffu, v, 2);
            rsum[m][pr] = v;
        }
    float* part = (float*)smem;           // [128][4]
    __syncthreads();
    if (qc == 0) {
        #pragma unroll
        for (int m = 0; m < 2; m++)
            #pragma unroll
            for (int pr = 0; pr < 2; pr++)
                part[(wm * 32 + m * 16 + qr + pr * 8) * 4 + wn] = rsum[m][pr];
    }
    __syncthreads();
    if (tid < 128) {
        float e = part[tid * 4 + 0] + part[tid * 4 + 1] + part[tid * 4 + 2] + part[tid * 4 + 3];
        g_epart[(size_t)bn * (MAXLEN * BATCH) + mt * 128 + tid] = e;
    }
}

// ---------------- generic M=64 GEMM ----------------
template <bool BT>
__global__ void gemm64(const float* __restrict__ A, const float* __restrict__ B,
                       const float* __restrict__ bias, float* __restrict__ C,
                       int N, int K, int ldc) {
    __shared__ float As[64][16];
    __shared__ float Bs[16][64];
    const int nT  = blockIdx.x * 64;
    const int tid = threadIdx.x;
    const int tx  = tid & 15, ty = tid >> 4;
    const int m4  = tid >> 2, kq = tid & 3;

    float acc[4][4] = {};
    for (int k0 = 0; k0 < K; k0 += 16) {
        float4 avv = *(const float4*)(A + (size_t)m4 * K + k0 + kq * 4);
        *(float4*)&As[m4][kq * 4] = avv;
        if (BT) {
            int n = tid >> 2;
            int gn = nT + n;
            float4 bv = make_float4(0.f, 0.f, 0.f, 0.f);
            if (gn < N) bv = *(const float4*)(B + (size_t)gn * K + k0 + kq * 4);
            Bs[kq * 4 + 0][n] = bv.x;
            Bs[kq * 4 + 1][n] = bv.y;
            Bs[kq * 4 + 2][n] = bv.z;
            Bs[kq * 4 + 3][n] = bv.w;
        } else {
            #pragma unroll
            for (int e2 = 0; e2 < 4; e2++) {
                int lin = tid + e2 * 256;
                int kk = lin >> 6, n = lin & 63;
                int gn = nT + n;
                Bs[kk][n] = (gn < N) ? B[(size_t)(k0 + kk) * N + gn] : 0.f;
            }
        }
        __syncthreads();
        #pragma unroll
        for (int kk = 0; kk < 16; kk++) {
            float4 b4 = *(const float4*)&Bs[kk][tx * 4];
            float bj[4] = {b4.x, b4.y, b4.z, b4.w};
            #pragma unroll
            for (int i = 0; i < 4; i++) {
                float a = As[ty * 4 + i][kk];
                #pragma unroll
                for (int j = 0; j < 4; j++) acc[i][j] = fmaf(a, bj[j], acc[i][j]);
            }
        }
        __syncthreads();
    }
    #pragma unroll
    for (int i = 0; i < 4; i++) {
        int m = ty * 4 + i;
        #pragma unroll
        for (int j = 0; j < 4; j++) {
            int n = nT + tx * 4 + j;
            if (n < N) {
                float v = acc[i][j];
                if (bias) v += bias[n];
                C[(size_t)m * ldc + n] = v;
            }
        }
    }
}

// ---------------- softmax over t ----------------
__global__ void softmax_kernel() {
    const int b = blockIdx.x;
    __shared__ float es[MAXLEN];
    __shared__ float red[256];
    const int tid = threadIdx.x;

    float mx = -1e30f;
    for (int t = tid; t < MAXLEN; t += 256) {
        float s = 0.f;
        #pragma unroll
        for (int p = 0; p < NCHUNK; p++) s += g_epart[p * (MAXLEN * BATCH) + t * 64 + b];
        es[t] = s;
        mx = fmaxf(mx, s);
    }
    red[tid] = mx; __syncthreads();
    for (int s2 = 128; s2; s2 >>= 1) {
        if (tid < s2) red[tid] = fmaxf(red[tid], red[tid + s2]);
        __syncthreads();
    }
    mx = red[0]; __syncthreads();

    float sum = 0.f;
    for (int t = tid; t < MAXLEN; t += 256) {
        float v = __expf(es[t] - mx);
        es[t] = v;
        sum += v;
    }
    red[tid] = sum; __syncthreads();
    for (int s2 = 128; s2; s2 >>= 1) {
        if (tid < s2) red[tid] += red[tid + s2];
        __syncthreads();
    }
    float inv = 1.f / red[0];
    for (int t = tid; t < MAXLEN; t += 256) g_alpha[t * 64 + b] = es[t] * inv;
}

// ---------------- context ----------------
__global__ void context_kernel(const float* __restrict__ E) {
    const int b = blockIdx.x, seg = blockIdx.y;
    const int h = threadIdx.x;
    float acc = 0.f;
    #pragma unroll 4
    for (int t = seg * 128; t < (seg + 1) * 128; t++)
        acc = fmaf(g_alpha[t * 64 + b], E[((size_t)t * 64 + b) * HID + h], acc);
    g_cpart[(seg * BATCH + b) * HID + h] = acc;
}

// ---------------- x = concat(embedding[cur], c) ----------------
__global__ void build_x(const int* __restrict__ cur, const float* __restrict__ emb) {
    const int b = blockIdx.x, tid = threadIdx.x;
    const int tok = cur[b];
    for (int k = tid; k < EMBED; k += 512)
        g_x[b * (EMBED + HID) + k] = emb[(size_t)tok * EMBED + k];
    for (int k = tid; k < HID; k += 512) {
        float s = 0.f;
        #pragma unroll
        for (int p = 0; p < 8; p++) s += g_cpart[(p * BATCH + b) * HID + k];
        g_x[b * (EMBED + HID) + EMBED + k] = s;
    }
}

// ---------------- GRU gates ----------------
__global__ void gru_gates(const float* __restrict__ hprev,
                          float* __restrict__ out1, float* __restrict__ out2) {
    const int idx = blockIdx.x * 256 + threadIdx.x;
    const int b = idx >> 10, q = idx & 1023;
    const float* gi = g_gi + b * 3072;
    const float* gh = g_gh + b * 3072;
    float ir = gi[q], iz = gi[q + 1024], in_ = gi[q + 2048];
    float hr = gh[q], hz = gh[q + 1024], hn = gh[q + 2048];
    float r = 1.f / (1.f + __expf(-(ir + hr)));
    float z = 1.f / (1.f + __expf(-(iz + hz)));
    float n = tanhf(in_ + r * hn);
    float h = (1.f - z) * n + z * hprev[idx];
    out1[idx] = h;
    if (out2) out2[idx] = h;
}

// ---------------- launch ----------------
extern "C" void kernel_launch(void* const* d_in, const int* in_sizes, int n_in,
                              void* d_out, int out_size) {
    const int*   cur    = (const int*)d_in[0];
    const float* state  = (const float*)d_in[1];
    const float* enc    = (const float*)d_in[2];
    const float* emb    = (const float*)d_in[3];
    const float* w_att1 = (const float*)d_in[4];
    const float* w_att2 = (const float*)d_in[5];
    const float* w_ih0  = (const float*)d_in[6];
    const float* w_hh0  = (const float*)d_in[7];
    const float* b_ih0  = (const float*)d_in[8];
    const float* b_hh0  = (const float*)d_in[9];
    const float* w_ih1  = (const float*)d_in[10];
    const float* w_hh1  = (const float*)d_in[11];
    const float* b_ih1  = (const float*)d_in[12];
    const float* b_hh1  = (const float*)d_in[13];
    const float* w_out  = (const float*)d_in[14];
    const float* b_out  = (const float*)d_in[15];

    float* out = (float*)d_out;
    float* st0 = out + (size_t)BATCH * VOCAB;
    float* st1 = st0 + BATCH * HID;

    float *p_dproj, *p_x, *p_gi, *p_gh, *p_h0;
    cudaGetSymbolAddress((void**)&p_dproj, g_dproj);
    cudaGetSymbolAddress((void**)&p_x,     g_x);
    cudaGetSymbolAddress((void**)&p_gi,    g_gi);
    cudaGetSymbolAddress((void**)&p_gh,    g_gh);
    cudaGetSymbolAddress((void**)&p_h0,    g_h0);

    cudaFuncSetAttribute(attn_mma, cudaFuncAttributeMaxDynamicSharedMemorySize,
                         SMEM_TOTAL_ATT);

    const float* dec = state + (size_t)BATCH * HID;

    // 0. prep: split weights + enc into fp16 hi/lo
    prep_b<<<dim3(32, 32), dim3(32, 8)>>>(w_att1);
    prep_enc<<<(MAXLEN * BATCH * HID) / (256 * 4), 256>>>(enc);
    // 1. dproj = dec @ w1_d
    gemm64<false><<<16, 256>>>(dec, w_att1 + (size_t)HID * HID, nullptr,
                               p_dproj, HID, HID, HID);
    // 2. attention energies: fp16x3 tensor-core GEMM + fused tanh/project
    attn_mma<<<dim3(NCHUNK, 512), 512, SMEM_TOTAL_ATT>>>(w_att2);
    // 3. softmax over time
    softmax_kernel<<<BATCH, 256>>>();
    // 4. context vector
    context_kernel<<<dim3(BATCH, 8), 1024>>>(enc);
    // 5. x = concat(emb, c)
    build_x<<<BATCH, 512>>>(cur, emb);
    // 6. GRU layer 0
    gemm64<true><<<48, 256>>>(p_x,   w_ih0, b_ih0, p_gi, 3 * HID, EMBED + HID, 3 * HID);
    gemm64<true><<<48, 256>>>(state, w_hh0, b_hh0, p_gh, 3 * HID, HID,         3 * HID);
    gru_gates<<<256, 256>>>(state, st0, p_h0);
    // 7. GRU layer 1
    gemm64<true><<<48, 256>>>(p_h0, w_ih1, b_ih1, p_gi, 3 * HID, HID, 3 * HID);
    gemm64<true><<<48, 256>>>(dec,  w_hh1, b_hh1, p_gh, 3 * HID, HID, 3 * HID);
    gru_gates<<<256, 256>>>(dec, st1, nullptr);
    // 8. logits
    gemm64<true><<<(VOCAB + 63) / 64, 256>>>(st1, w_out, b_out, out, VOCAB, HID, VOCAB);
}

// round 6
// speedup vs baseline: 1.0524x; 1.0524x over previous
#include <cuda_runtime.h>
#include <cuda_fp16.h>
#include <cstdint>
#include <cstddef>

#define HID    1024
#define EMBED  512
#define BATCH  64
#define MAXLEN 1024
#define VOCAB  50257
#define NCHUNK 8            // 1024 attn dims / 128 per block

// ---------------- scratch (no allocations allowed) ----------------
__device__ float  g_dproj[BATCH * HID];
__device__ float  g_epart[NCHUNK * MAXLEN * BATCH];
__device__ float  g_alpha[MAXLEN * BATCH];
__device__ float  g_cpart[8 * BATCH * HID];
__device__ float  g_x[BATCH * (EMBED + HID)];
__device__ float  g_gi[BATCH * 3 * HID];
__device__ float  g_gh[BATCH * 3 * HID];
__device__ float  g_h0[BATCH * HID];
__device__ __half g_bh[HID * HID];                  // w1e^T fp16-hi [n][k]
__device__ __half g_bl[HID * HID];                  // w1e^T fp16-lo [n][k]
__device__ __half g_eh[(size_t)MAXLEN * BATCH * HID];   // enc fp16-hi
__device__ __half g_el[(size_t)MAXLEN * BATCH * HID];   // enc fp16-lo

// ---------------- prep: transpose + fp16-split w1e ----------------
__global__ void prep_b(const float* __restrict__ w1e) {
    __shared__ float tile[32][33];
    int k0 = blockIdx.x * 32, n0 = blockIdx.y * 32;
    int tx = threadIdx.x, ty = threadIdx.y;
    for (int i = ty; i < 32; i += 8)
        tile[i][tx] = w1e[(size_t)(k0 + i) * HID + n0 + tx];
    __syncthreads();
    for (int i = ty; i < 32; i += 8) {
        float v = tile[tx][i];
        __half hi = __float2half_rn(v);
        __half lo = __float2half_rn(v - __half2float(hi));
        g_bh[(size_t)(n0 + i) * HID + k0 + tx] = hi;
        g_bl[(size_t)(n0 + i) * HID + k0 + tx] = lo;
    }
}

// ---------------- prep: fp16-split enc_states ----------------
__global__ void prep_enc(const float* __restrict__ enc) {
    size_t i = ((size_t)blockIdx.x * 256 + threadIdx.x) * 4;
    float4 v = *(const float4*)(enc + i);
    __half h[4], l[4];
    float x[4] = {v.x, v.y, v.z, v.w};
    #pragma unroll
    for (int e = 0; e < 4; e++) {
        h[e] = __float2half_rn(x[e]);
        l[e] = __float2half_rn(x[e] - __half2float(h[e]));
    }
    *(uint2*)(g_eh + i) = *(uint2*)h;
    *(uint2*)(g_el + i) = *(uint2*)l;
}

// ---------------- helpers ----------------
__device__ __forceinline__ uint32_t smem_u32(const void* p) {
    uint32_t a;
    asm("{ .reg .u64 t; cvta.to.shared.u64 t, %1; cvt.u32.u64 %0, t; }" : "=r"(a) : "l"(p));
    return a;
}
__device__ __forceinline__ void cp16(void* s, const void* g) {
    asm volatile("cp.async.cg.shared.global [%0], [%1], 16;"
                 :: "r"(smem_u32(s)), "l"(g));
}
__device__ __forceinline__ void cp_commit() {
    asm volatile("cp.async.commit_group;" ::: "memory");
}
template <int N>
__device__ __forceinline__ void cp_wait() {
    asm volatile("cp.async.wait_group %0;" :: "n"(N) : "memory");
}
__device__ __forceinline__ void mma16816(float* d, const uint32_t* a, const uint32_t* b) {
    asm volatile("mma.sync.aligned.m16n8k16.row.col.f32.f16.f16.f32 "
                 "{%0,%1,%2,%3}, {%4,%5,%6,%7}, {%8,%9}, {%0,%1,%2,%3};"
                 : "+f"(d[0]), "+f"(d[1]), "+f"(d[2]), "+f"(d[3])
                 : "r"(a[0]), "r"(a[1]), "r"(a[2]), "r"(a[3]),
                   "r"(b[0]), "r"(b[1]));
}
__device__ __forceinline__ void ldsm4(uint32_t* r, uint32_t addr) {
    asm volatile("ldmatrix.sync.aligned.m8n8.x4.shared.b16 {%0,%1,%2,%3}, [%4];"
                 : "=r"(r[0]), "=r"(r[1]), "=r"(r[2]), "=r"(r[3]) : "r"(addr));
}

// ---------------- attention GEMM: 512 thr, ldmatrix, KC=64, 3-stage cp.async ----------------
// block 128 rows x 128 attn dims, K=1024 in 64-chunks. warp tile 32x32.
// smem row stride 72 halves (144B): ldmatrix conflict-free (9r mod 16 distinct).
#define ASTRIDE 72
#define MATH (128 * ASTRIDE)          // halves per tile
#define STAGE_BYTES (4 * MATH * 2)    // sAh sAl sBh sBl
#define NSTAGE 3
#define SMEM_TOTAL_ATT (NSTAGE * STAGE_BYTES)
#define KC 64
#define KT (HID / KC)                 // 16

__global__ void __launch_bounds__(512, 1)
attn_mma(const float* __restrict__ w2) {
    extern __shared__ char smem[];
    const uint32_t sbase = smem_u32(smem);
    const int bn = blockIdx.x;       // 0..7   n-chunk
    const int mt = blockIdx.y;       // 0..511 row tile
    const int tid = threadIdx.x;
    const int wid = tid >> 5, lane = tid & 31;
    const int wm = wid >> 2, wn = wid & 3;     // warps: 4(M) x 4(N)
    const int qr = lane >> 2, qc = lane & 3;

    const __half* gAh = g_eh + (size_t)mt * 128 * HID;
    const __half* gAl = g_el + (size_t)mt * 128 * HID;
    const __half* gBh = g_bh + (size_t)(bn * 128) * HID;
    const __half* gBl = g_bl + (size_t)(bn * 128) * HID;

    const int lr = tid >> 2, lc = tid & 3;     // loader: 128 rows x {lc, lc+4} chunks

    auto issue_load = [&](int kt) {
        char* base = smem + (kt % NSTAGE) * STAGE_BYTES;
        __half* sAh = (__half*)base;
        __half* sAl = sAh + MATH;
        __half* sBh = sAl + MATH;
        __half* sBl = sBh + MATH;
        #pragma unroll
        for (int i = 0; i < 2; i++) {
            int c = lc + i * 4;                       // 16B chunk 0..7
            size_t go = (size_t)lr * HID + kt * KC + c * 8;
            int so = lr * ASTRIDE + c * 8;
            cp16(sAh + so, gAh + go);
            cp16(sAl + so, gAl + go);
            cp16(sBh + so, gBh + go);
            cp16(sBl + so, gBl + go);
        }
        cp_commit();
    };

    // ldmatrix per-lane byte offsets (within a tile)
    // A (m16k16 frag, x4): lane l -> row base+(l&15), col (l>>4)*8
    int offA[2];
    #pragma unroll
    for (int m = 0; m < 2; m++)
        offA[m] = ((wm * 32 + m * 16 + (lane & 15)) * ASTRIDE + (lane >> 4) * 8) * 2;
    // B (two n8k16 frags per x4): lane l -> ntile 2j+(l>>4), col ((l>>3)&1)*8, row (l&7)
    int offB[2];
    #pragma unroll
    for (int j = 0; j < 2; j++)
        offB[j] = ((wn * 32 + (2 * j + (lane >> 4)) * 8 + (lane & 7)) * ASTRIDE
                   + ((lane >> 3) & 1) * 8) * 2;

    float acc[2][4][4] = {};

    auto compute = [&](int kt) {
        const uint32_t base = sbase + (kt % NSTAGE) * STAGE_BYTES;
        const uint32_t uAh = base;
        const uint32_t uAl = base + MATH * 2;
        const uint32_t uBh = base + 2 * MATH * 2;
        const uint32_t uBl = base + 3 * MATH * 2;
        #pragma unroll
        for (int ks = 0; ks < KC; ks += 16) {
            uint32_t ah[2][4], al[2][4], bh[4][2], bl[4][2];
            #pragma unroll
            for (int m = 0; m < 2; m++) {
                ldsm4(ah[m], uAh + offA[m] + ks * 2);
                ldsm4(al[m], uAl + offA[m] + ks * 2);
            }
            #pragma unroll
            for (int j = 0; j < 2; j++) {
                uint32_t r[4];
                ldsm4(r, uBh + offB[j] + ks * 2);
                bh[2 * j][0] = r[0]; bh[2 * j][1] = r[1];
                bh[2 * j + 1][0] = r[2]; bh[2 * j + 1][1] = r[3];
                ldsm4(r, uBl + offB[j] + ks * 2);
                bl[2 * j][0] = r[0]; bl[2 * j][1] = r[1];
                bl[2 * j + 1][0] = r[2]; bl[2 * j + 1][1] = r[3];
            }
            #pragma unroll
            for (int m = 0; m < 2; m++)
                #pragma unroll
                for (int n = 0; n < 4; n++) mma16816(acc[m][n], ah[m], bh[n]);
            #pragma unroll
            for (int m = 0; m < 2; m++)
                #pragma unroll
                for (int n = 0; n < 4; n++) mma16816(acc[m][n], al[m], bh[n]);
            #pragma unroll
            for (int m = 0; m < 2; m++)
                #pragma unroll
                for (int n = 0; n < 4; n++) mma16816(acc[m][n], ah[m], bl[n]);
        }
    };

    issue_load(0);
    issue_load(1);
    for (int kt = 0; kt < KT; kt++) {
        cp_wait<1>();
        __syncthreads();
        if (kt + 2 < KT) issue_load(kt + 2);
        else cp_commit();                 // keep group count stable for wait<1>
        compute(kt);
    }

    // ---- epilogue: e_partial[row] = sum_n tanh(acc + dproj[b][n]) * w2[n] ----
    float rsum[2][2] = {};
    #pragma unroll
    for (int m = 0; m < 2; m++) {
        #pragma unroll
        for (int n = 0; n < 4; n++) {
            int ng0 = bn * 128 + wn * 32 + n * 8 + qc * 2;
            float w20 = w2[ng0], w21 = w2[ng0 + 1];
            #pragma unroll
            for (int pr = 0; pr < 2; pr++) {
                int row_local = wm * 32 + m * 16 + qr + pr * 8;
                int b = row_local & 63;
                const float* dp = g_dproj + (size_t)b * HID + ng0;
                rsum[m][pr] += tanhf(acc[m][n][pr * 2 + 0] + dp[0]) * w20
                             + tanhf(acc[m][n][pr * 2 + 1] + dp[1]) * w21;
            }
        }
    }
    #pragma unroll
    for (int m = 0; m < 2; m++)
        #pragma unroll
        for (int pr = 0; pr < 2; pr++) {
            float v = rsum[m][pr];
            v += __shfl_xor_sync(0xffffffffu, v, 1);
            v += __shfl_xor_sync(0xffffffffu, v, 2);
            rsum[m][pr] = v;
        }
    float* part = (float*)smem;           // [128][4]
    __syncthreads();
    if (qc == 0) {
        #pragma unroll
        for (int m = 0; m < 2; m++)
            #pragma unroll
            for (int pr = 0; pr < 2; pr++)
                part[(wm * 32 + m * 16 + qr + pr * 8) * 4 + wn] = rsum[m][pr];
    }
    __syncthreads();
    if (tid < 128) {
        float e = part[tid * 4 + 0] + part[tid * 4 + 1] + part[tid * 4 + 2] + part[tid * 4 + 3];
        g_epart[(size_t)bn * (MAXLEN * BATCH) + mt * 128 + tid] = e;
    }
}

// ---------------- generic M=64 GEMM ----------------
template <bool BT>
__global__ void gemm64(const float* __restrict__ A, const float* __restrict__ B,
                       const float* __restrict__ bias, float* __restrict__ C,
                       int N, int K, int ldc) {
    __shared__ float As[64][16];
    __shared__ float Bs[16][64];
    const int nT  = blockIdx.x * 64;
    const int tid = threadIdx.x;
    const int tx  = tid & 15, ty = tid >> 4;
    const int m4  = tid >> 2, kq = tid & 3;

    float acc[4][4] = {};
    for (int k0 = 0; k0 < K; k0 += 16) {
        float4 avv = *(const float4*)(A + (size_t)m4 * K + k0 + kq * 4);
        *(float4*)&As[m4][kq * 4] = avv;
        if (BT) {
            int n = tid >> 2;
            int gn = nT + n;
            float4 bv = make_float4(0.f, 0.f, 0.f, 0.f);
            if (gn < N) bv = *(const float4*)(B + (size_t)gn * K + k0 + kq * 4);
            Bs[kq * 4 + 0][n] = bv.x;
            Bs[kq * 4 + 1][n] = bv.y;
            Bs[kq * 4 + 2][n] = bv.z;
            Bs[kq * 4 + 3][n] = bv.w;
        } else {
            #pragma unroll
            for (int e2 = 0; e2 < 4; e2++) {
                int lin = tid + e2 * 256;
                int kk = lin >> 6, n = lin & 63;
                int gn = nT + n;
                Bs[kk][n] = (gn < N) ? B[(size_t)(k0 + kk) * N + gn] : 0.f;
            }
        }
        __syncthreads();
        #pragma unroll
        for (int kk = 0; kk < 16; kk++) {
            float4 b4 = *(const float4*)&Bs[kk][tx * 4];
            float bj[4] = {b4.x, b4.y, b4.z, b4.w};
            #pragma unroll
            for (int i = 0; i < 4; i++) {
                float a = As[ty * 4 + i][kk];
                #pragma unroll
                for (int j = 0; j < 4; j++) acc[i][j] = fmaf(a, bj[j], acc[i][j]);
            }
        }
        __syncthreads();
    }
    #pragma unroll
    for (int i = 0; i < 4; i++) {
        int m = ty * 4 + i;
        #pragma unroll
        for (int j = 0; j < 4; j++) {
            int n = nT + tx * 4 + j;
            if (n < N) {
                float v = acc[i][j];
                if (bias) v += bias[n];
                C[(size_t)m * ldc + n] = v;
            }
        }
    }
}

// ---------------- softmax over t ----------------
__global__ void softmax_kernel() {
    const int b = blockIdx.x;
    __shared__ float es[MAXLEN];
    __shared__ float red[256];
    const int tid = threadIdx.x;

    float mx = -1e30f;
    for (int t = tid; t < MAXLEN; t += 256) {
        float s = 0.f;
        #pragma unroll
        for (int p = 0; p < NCHUNK; p++) s += g_epart[p * (MAXLEN * BATCH) + t * 64 + b];
        es[t] = s;
        mx = fmaxf(mx, s);
    }
    red[tid] = mx; __syncthreads();
    for (int s2 = 128; s2; s2 >>= 1) {
        if (tid < s2) red[tid] = fmaxf(red[tid], red[tid + s2]);
        __syncthreads();
    }
    mx = red[0]; __syncthreads();

    float sum = 0.f;
    for (int t = tid; t < MAXLEN; t += 256) {
        float v = __expf(es[t] - mx);
        es[t] = v;
        sum += v;
    }
    red[tid] = sum; __syncthreads();
    for (int s2 = 128; s2; s2 >>= 1) {
        if (tid < s2) red[tid] += red[tid + s2];
        __syncthreads();
    }
    float inv = 1.f / red[0];
    for (int t = tid; t < MAXLEN; t += 256) g_alpha[t * 64 + b] = es[t] * inv;
}

// ---------------- context ----------------
__global__ void context_kernel(const float* __restrict__ E) {
    const int b = blockIdx.x, seg = blockIdx.y;
    const int h = threadIdx.x;
    float acc = 0.f;
    #pragma unroll 4
    for (int t = seg * 128; t < (seg + 1) * 128; t++)
        acc = fmaf(g_alpha[t * 64 + b], E[((size_t)t * 64 + b) * HID + h], acc);
    g_cpart[(seg * BATCH + b) * HID + h] = acc;
}

// ---------------- x = concat(embedding[cur], c) ----------------
__global__ void build_x(const int* __restrict__ cur, const float* __restrict__ emb) {
    const int b = blockIdx.x, tid = threadIdx.x;
    const int tok = cur[b];
    for (int k = tid; k < EMBED; k += 512)
        g_x[b * (EMBED + HID) + k] = emb[(size_t)tok * EMBED + k];
    for (int k = tid; k < HID; k += 512) {
        float s = 0.f;
        #pragma unroll
        for (int p = 0; p < 8; p++) s += g_cpart[(p * BATCH + b) * HID + k];
        g_x[b * (EMBED + HID) + EMBED + k] = s;
    }
}

// ---------------- GRU gates ----------------
__global__ void gru_gates(const float* __restrict__ hprev,
                          float* __restrict__ out1, float* __restrict__ out2) {
    const int idx = blockIdx.x * 256 + threadIdx.x;
    const int b = idx >> 10, q = idx & 1023;
    const float* gi = g_gi + b * 3072;
    const float* gh = g_gh + b * 3072;
    float ir = gi[q], iz = gi[q + 1024], in_ = gi[q + 2048];
    float hr = gh[q], hz = gh[q + 1024], hn = gh[q + 2048];
    float r = 1.f / (1.f + __expf(-(ir + hr)));
    float z = 1.f / (1.f + __expf(-(iz + hz)));
    float n = tanhf(in_ + r * hn);
    float h = (1.f - z) * n + z * hprev[idx];
    out1[idx] = h;
    if (out2) out2[idx] = h;
}

// ---------------- launch ----------------
extern "C" void kernel_launch(void* const* d_in, const int* in_sizes, int n_in,
                              void* d_out, int out_size) {
    const int*   cur    = (const int*)d_in[0];
    const float* state  = (const float*)d_in[1];
    const float* enc    = (const float*)d_in[2];
    const float* emb    = (const float*)d_in[3];
    const float* w_att1 = (const float*)d_in[4];
    const float* w_att2 = (const float*)d_in[5];
    const float* w_ih0  = (const float*)d_in[6];
    const float* w_hh0  = (const float*)d_in[7];
    const float* b_ih0  = (const float*)d_in[8];
    const float* b_hh0  = (const float*)d_in[9];
    const float* w_ih1  = (const float*)d_in[10];
    const float* w_hh1  = (const float*)d_in[11];
    const float* b_ih1  = (const float*)d_in[12];
    const float* b_hh1  = (const float*)d_in[13];
    const float* w_out  = (const float*)d_in[14];
    const float* b_out  = (const float*)d_in[15];

    float* out = (float*)d_out;
    float* st0 = out + (size_t)BATCH * VOCAB;
    float* st1 = st0 + BATCH * HID;

    float *p_dproj, *p_x, *p_gi, *p_gh, *p_h0;
    cudaGetSymbolAddress((void**)&p_dproj, g_dproj);
    cudaGetSymbolAddress((void**)&p_x,     g_x);
    cudaGetSymbolAddress((void**)&p_gi,    g_gi);
    cudaGetSymbolAddress((void**)&p_gh,    g_gh);
    cudaGetSymbolAddress((void**)&p_h0,    g_h0);

    cudaFuncSetAttribute(attn_mma, cudaFuncAttributeMaxDynamicSharedMemorySize,
                         SMEM_TOTAL_ATT);

    const float* dec = state + (size_t)BATCH * HID;

    // 0. prep: split weights + enc into fp16 hi/lo
    prep_b<<<dim3(32, 32), dim3(32, 8)>>>(w_att1);
    prep_enc<<<(MAXLEN * BATCH * HID) / (256 * 4), 256>>>(enc);
    // 1. dproj = dec @ w1_d
    gemm64<false><<<16, 256>>>(dec, w_att1 + (size_t)HID * HID, nullptr,
                               p_dproj, HID, HID, HID);
    // 2. attention energies: fp16x3 tensor-core GEMM + fused tanh/project
    attn_mma<<<dim3(NCHUNK, 512), 512, SMEM_TOTAL_ATT>>>(w_att2);
    // 3. softmax over time
    softmax_kernel<<<BATCH, 256>>>();
    // 4. context vector
    context_kernel<<<dim3(BATCH, 8), 1024>>>(enc);
    // 5. x = concat(emb, c)
    build_x<<<BATCH, 512>>>(cur, emb);
    // 6. GRU layer 0
    gemm64<true><<<48, 256>>>(p_x,   w_ih0, b_ih0, p_gi, 3 * HID, EMBED + HID, 3 * HID);
    gemm64<true><<<48, 256>>>(state, w_hh0, b_hh0, p_gh, 3 * HID, HID,         3 * HID);
    gru_gates<<<256, 256>>>(state, st0, p_h0);
    // 7. GRU layer 1
    gemm64<true><<<48, 256>>>(p_h0, w_ih1, b_ih1, p_gi, 3 * HID, HID, 3 * HID);
    gemm64<true><<<48, 256>>>(dec,  w_hh1, b_hh1, p_gh, 3 * HID, HID, 3 * HID);
    gru_gates<<<256, 256>>>(dec, st1, nullptr);
    // 8. logits
    gemm64<true><<<(VOCAB + 63) / 64, 256>>>(st1, w_out, b_out, out, VOCAB, HID, VOCAB);
}

// round 7
// speedup vs baseline: 1.3116x; 1.2463x over previous
#include <cuda_runtime.h>
#include <cuda_fp16.h>
#include <cstdint>
#include <cstddef>

#define HID    1024
#define EMBED  512
#define BATCH  64
#define MAXLEN 1024
#define VOCAB  50257
#define NCHUNK 8            // 1024 attn dims / 128 per block

// ---------------- scratch (no allocations allowed) ----------------
__device__ float  g_dproj[BATCH * HID];
__device__ float  g_epart[NCHUNK * MAXLEN * BATCH];
__device__ float  g_alpha[MAXLEN * BATCH];
__device__ float  g_cpart[8 * BATCH * HID];
__device__ float  g_x[BATCH * (EMBED + HID)];
__device__ float  g_gi[BATCH * 3 * HID];
__device__ float  g_gh[BATCH * 3 * HID];
__device__ float  g_h0[BATCH * HID];
__device__ __half g_bh[HID * HID];                  // w1e^T fp16-hi [n][k]
__device__ __half g_bl[HID * HID];                  // w1e^T fp16-lo [n][k]
__device__ __half g_eh[(size_t)MAXLEN * BATCH * HID];   // enc fp16-hi

// ---------------- prep: transpose + fp16-split w1e ----------------
__global__ void prep_b(const float* __restrict__ w1e) {
    __shared__ float tile[32][33];
    int k0 = blockIdx.x * 32, n0 = blockIdx.y * 32;
    int tx = threadIdx.x, ty = threadIdx.y;
    for (int i = ty; i < 32; i += 8)
        tile[i][tx] = w1e[(size_t)(k0 + i) * HID + n0 + tx];
    __syncthreads();
    for (int i = ty; i < 32; i += 8) {
        float v = tile[tx][i];
        __half hi = __float2half_rn(v);
        __half lo = __float2half_rn(v - __half2float(hi));
        g_bh[(size_t)(n0 + i) * HID + k0 + tx] = hi;
        g_bl[(size_t)(n0 + i) * HID + k0 + tx] = lo;
    }
}

// ---------------- prep: fp16 enc_states (hi only) ----------------
__global__ void prep_enc(const float* __restrict__ enc) {
    size_t i = ((size_t)blockIdx.x * 256 + threadIdx.x) * 4;
    float4 v = *(const float4*)(enc + i);
    __half h[4];
    h[0] = __float2half_rn(v.x);
    h[1] = __float2half_rn(v.y);
    h[2] = __float2half_rn(v.z);
    h[3] = __float2half_rn(v.w);
    *(uint2*)(g_eh + i) = *(uint2*)h;
}

// ---------------- helpers ----------------
__device__ __forceinline__ uint32_t smem_u32(const void* p) {
    uint32_t a;
    asm("{ .reg .u64 t; cvta.to.shared.u64 t, %1; cvt.u32.u64 %0, t; }" : "=r"(a) : "l"(p));
    return a;
}
__device__ __forceinline__ void cp16(void* s, const void* g) {
    asm volatile("cp.async.cg.shared.global [%0], [%1], 16;"
                 :: "r"(smem_u32(s)), "l"(g));
}
__device__ __forceinline__ void cp_commit() {
    asm volatile("cp.async.commit_group;" ::: "memory");
}
template <int N>
__device__ __forceinline__ void cp_wait() {
    asm volatile("cp.async.wait_group %0;" :: "n"(N) : "memory");
}
__device__ __forceinline__ void mma16816(float* d, const uint32_t* a, const uint32_t* b) {
    asm volatile("mma.sync.aligned.m16n8k16.row.col.f32.f16.f16.f32 "
                 "{%0,%1,%2,%3}, {%4,%5,%6,%7}, {%8,%9}, {%0,%1,%2,%3};"
                 : "+f"(d[0]), "+f"(d[1]), "+f"(d[2]), "+f"(d[3])
                 : "r"(a[0]), "r"(a[1]), "r"(a[2]), "r"(a[3]),
                   "r"(b[0]), "r"(b[1]));
}
__device__ __forceinline__ void ldsm4(uint32_t* r, uint32_t addr) {
    asm volatile("ldmatrix.sync.aligned.m8n8.x4.shared.b16 {%0,%1,%2,%3}, [%4];"
                 : "=r"(r[0]), "=r"(r[1]), "=r"(r[2]), "=r"(r[3]) : "r"(addr));
}

// ---------------- attention GEMM: 2-pass fp16 (Ah*Bh + Ah*Bl), ldmatrix, 4-stage ----------------
// block 128 rows x 128 attn dims, K=1024 in 64-chunks. warp tile 32x32.
// smem row stride 72 halves (144B): ldmatrix conflict-free.
#define ASTRIDE 72
#define MATH (128 * ASTRIDE)          // halves per tile
#define STAGE_BYTES (3 * MATH * 2)    // sAh sBh sBl = 55296 B
#define NSTAGE 4
#define SMEM_TOTAL_ATT (NSTAGE * STAGE_BYTES)   // 221184 B
#define KC 64
#define KT (HID / KC)                 // 16

__global__ void __launch_bounds__(512, 1)
attn_mma(const float* __restrict__ w2) {
    extern __shared__ char smem[];
    const uint32_t sbase = smem_u32(smem);
    const int bn = blockIdx.x;       // 0..7   n-chunk
    const int mt = blockIdx.y;       // 0..511 row tile
    const int tid = threadIdx.x;
    const int wid = tid >> 5, lane = tid & 31;
    const int wm = wid >> 2, wn = wid & 3;     // warps: 4(M) x 4(N)
    const int qr = lane >> 2, qc = lane & 3;

    const __half* gAh = g_eh + (size_t)mt * 128 * HID;
    const __half* gBh = g_bh + (size_t)(bn * 128) * HID;
    const __half* gBl = g_bl + (size_t)(bn * 128) * HID;

    const int lr = tid >> 2, lc = tid & 3;     // loader: 128 rows x {lc, lc+4} chunks

    auto issue_load = [&](int kt) {
        char* base = smem + (kt % NSTAGE) * STAGE_BYTES;
        __half* sAh = (__half*)base;
        __half* sBh = sAh + MATH;
        __half* sBl = sBh + MATH;
        #pragma unroll
        for (int i = 0; i < 2; i++) {
            int c = lc + i * 4;                       // 16B chunk 0..7
            size_t go = (size_t)lr * HID + kt * KC + c * 8;
            int so = lr * ASTRIDE + c * 8;
            cp16(sAh + so, gAh + go);
            cp16(sBh + so, gBh + go);
            cp16(sBl + so, gBl + go);
        }
        cp_commit();
    };

    // ldmatrix per-lane byte offsets (within a tile)
    int offA[2];
    #pragma unroll
    for (int m = 0; m < 2; m++)
        offA[m] = ((wm * 32 + m * 16 + (lane & 15)) * ASTRIDE + (lane >> 4) * 8) * 2;
    int offB[2];
    #pragma unroll
    for (int j = 0; j < 2; j++)
        offB[j] = ((wn * 32 + (2 * j + (lane >> 4)) * 8 + (lane & 7)) * ASTRIDE
                   + ((lane >> 3) & 1) * 8) * 2;

    float acc[2][4][4] = {};

    auto compute = [&](int kt) {
        const uint32_t base = sbase + (kt % NSTAGE) * STAGE_BYTES;
        const uint32_t uAh = base;
        const uint32_t uBh = base + MATH * 2;
        const uint32_t uBl = base + 2 * MATH * 2;
        #pragma unroll
        for (int ks = 0; ks < KC; ks += 16) {
            uint32_t ah[2][4], bh[4][2], bl[4][2];
            #pragma unroll
            for (int m = 0; m < 2; m++)
                ldsm4(ah[m], uAh + offA[m] + ks * 2);
            #pragma unroll
            for (int j = 0; j < 2; j++) {
                uint32_t r[4];
                ldsm4(r, uBh + offB[j] + ks * 2);
                bh[2 * j][0] = r[0]; bh[2 * j][1] = r[1];
                bh[2 * j + 1][0] = r[2]; bh[2 * j + 1][1] = r[3];
                ldsm4(r, uBl + offB[j] + ks * 2);
                bl[2 * j][0] = r[0]; bl[2 * j][1] = r[1];
                bl[2 * j + 1][0] = r[2]; bl[2 * j + 1][1] = r[3];
            }
            #pragma unroll
            for (int m = 0; m < 2; m++)
                #pragma unroll
                for (int n = 0; n < 4; n++) mma16816(acc[m][n], ah[m], bh[n]);
            #pragma unroll
            for (int m = 0; m < 2; m++)
                #pragma unroll
                for (int n = 0; n < 4; n++) mma16816(acc[m][n], ah[m], bl[n]);
        }
    };

    issue_load(0);
    issue_load(1);
    issue_load(2);
    for (int kt = 0; kt < KT; kt++) {
        cp_wait<2>();
        __syncthreads();
        if (kt + 3 < KT) issue_load(kt + 3);
        else cp_commit();                 // keep group count stable
        compute(kt);
    }

    // ---- epilogue: e_partial[row] = sum_n tanh(acc + dproj[b][n]) * w2[n] ----
    float rsum[2][2] = {};
    #pragma unroll
    for (int m = 0; m < 2; m++) {
        #pragma unroll
        for (int n = 0; n < 4; n++) {
            int ng0 = bn * 128 + wn * 32 + n * 8 + qc * 2;
            float w20 = w2[ng0], w21 = w2[ng0 + 1];
            #pragma unroll
            for (int pr = 0; pr < 2; pr++) {
                int row_local = wm * 32 + m * 16 + qr + pr * 8;
                int b = row_local & 63;
                const float* dp = g_dproj + (size_t)b * HID + ng0;
                rsum[m][pr] += tanhf(acc[m][n][pr * 2 + 0] + dp[0]) * w20
                             + tanhf(acc[m][n][pr * 2 + 1] + dp[1]) * w21;
            }
        }
    }
    #pragma unroll
    for (int m = 0; m < 2; m++)
        #pragma unroll
        for (int pr = 0; pr < 2; pr++) {
            float v = rsum[m][pr];
            v += __shfl_xor_sync(0xffffffffu, v, 1);
            v += __shfl_xor_sync(0xffffffffu, v, 2);
            rsum[m][pr] = v;
        }
    float* part = (float*)smem;           // [128][4]
    __syncthreads();
    if (qc == 0) {
        #pragma unroll
        for (int m = 0; m < 2; m++)
            #pragma unroll
            for (int pr = 0; pr < 2; pr++)
                part[(wm * 32 + m * 16 + qr + pr * 8) * 4 + wn] = rsum[m][pr];
    }
    __syncthreads();
    if (tid < 128) {
        float e = part[tid * 4 + 0] + part[tid * 4 + 1] + part[tid * 4 + 2] + part[tid * 4 + 3];
        g_epart[(size_t)bn * (MAXLEN * BATCH) + mt * 128 + tid] = e;
    }
}

// ---------------- generic M=64 GEMM ----------------
template <bool BT>
__global__ void gemm64(const float* __restrict__ A, const float* __restrict__ B,
                       const float* __restrict__ bias, float* __restrict__ C,
                       int N, int K, int ldc) {
    __shared__ float As[64][16];
    __shared__ float Bs[16][64];
    const int nT  = blockIdx.x * 64;
    const int tid = threadIdx.x;
    const int tx  = tid & 15, ty = tid >> 4;
    const int m4  = tid >> 2, kq = tid & 3;

    float acc[4][4] = {};
    for (int k0 = 0; k0 < K; k0 += 16) {
        float4 avv = *(const float4*)(A + (size_t)m4 * K + k0 + kq * 4);
        *(float4*)&As[m4][kq * 4] = avv;
        if (BT) {
            int n = tid >> 2;
            int gn = nT + n;
            float4 bv = make_float4(0.f, 0.f, 0.f, 0.f);
            if (gn < N) bv = *(const float4*)(B + (size_t)gn * K + k0 + kq * 4);
            Bs[kq * 4 + 0][n] = bv.x;
            Bs[kq * 4 + 1][n] = bv.y;
            Bs[kq * 4 + 2][n] = bv.z;
            Bs[kq * 4 + 3][n] = bv.w;
        } else {
            #pragma unroll
            for (int e2 = 0; e2 < 4; e2++) {
                int lin = tid + e2 * 256;
                int kk = lin >> 6, n = lin & 63;
                int gn = nT + n;
                Bs[kk][n] = (gn < N) ? B[(size_t)(k0 + kk) * N + gn] : 0.f;
            }
        }
        __syncthreads();
        #pragma unroll
        for (int kk = 0; kk < 16; kk++) {
            float4 b4 = *(const float4*)&Bs[kk][tx * 4];
            float bj[4] = {b4.x, b4.y, b4.z, b4.w};
            #pragma unroll
            for (int i = 0; i < 4; i++) {
                float a = As[ty * 4 + i][kk];
                #pragma unroll
                for (int j = 0; j < 4; j++) acc[i][j] = fmaf(a, bj[j], acc[i][j]);
            }
        }
        __syncthreads();
    }
    #pragma unroll
    for (int i = 0; i < 4; i++) {
        int m = ty * 4 + i;
        #pragma unroll
        for (int j = 0; j < 4; j++) {
            int n = nT + tx * 4 + j;
            if (n < N) {
                float v = acc[i][j];
                if (bias) v += bias[n];
                C[(size_t)m * ldc + n] = v;
            }
        }
    }
}

// ---------------- softmax over t ----------------
__global__ void softmax_kernel() {
    const int b = blockIdx.x;
    __shared__ float es[MAXLEN];
    __shared__ float red[256];
    const int tid = threadIdx.x;

    float mx = -1e30f;
    for (int t = tid; t < MAXLEN; t += 256) {
        float s = 0.f;
        #pragma unroll
        for (int p = 0; p < NCHUNK; p++) s += g_epart[p * (MAXLEN * BATCH) + t * 64 + b];
        es[t] = s;
        mx = fmaxf(mx, s);
    }
    red[tid] = mx; __syncthreads();
    for (int s2 = 128; s2; s2 >>= 1) {
        if (tid < s2) red[tid] = fmaxf(red[tid], red[tid + s2]);
        __syncthreads();
    }
    mx = red[0]; __syncthreads();

    float sum = 0.f;
    for (int t = tid; t < MAXLEN; t += 256) {
        float v = __expf(es[t] - mx);
        es[t] = v;
        sum += v;
    }
    red[tid] = sum; __syncthreads();
    for (int s2 = 128; s2; s2 >>= 1) {
        if (tid < s2) red[tid] += red[tid + s2];
        __syncthreads();
    }
    float inv = 1.f / red[0];
    for (int t = tid; t < MAXLEN; t += 256) g_alpha[t * 64 + b] = es[t] * inv;
}

// ---------------- context ----------------
__global__ void context_kernel(const float* __restrict__ E) {
    const int b = blockIdx.x, seg = blockIdx.y;
    const int h = threadIdx.x;
    float acc = 0.f;
    #pragma unroll 4
    for (int t = seg * 128; t < (seg + 1) * 128; t++)
        acc = fmaf(g_alpha[t * 64 + b], E[((size_t)t * 64 + b) * HID + h], acc);
    g_cpart[(seg * BATCH + b) * HID + h] = acc;
}

// ---------------- x = concat(embedding[cur], c) ----------------
__global__ void build_x(const int* __restrict__ cur, const float* __restrict__ emb) {
    const int b = blockIdx.x, tid = threadIdx.x;
    const int tok = cur[b];
    for (int k = tid; k < EMBED; k += 512)
        g_x[b * (EMBED + HID) + k] = emb[(size_t)tok * EMBED + k];
    for (int k = tid; k < HID; k += 512) {
        float s = 0.f;
        #pragma unroll
        for (int p = 0; p < 8; p++) s += g_cpart[(p * BATCH + b) * HID + k];
        g_x[b * (EMBED + HID) + EMBED + k] = s;
    }
}

// ---------------- GRU gates ----------------
__global__ void gru_gates(const float* __restrict__ hprev,
                          float* __restrict__ out1, float* __restrict__ out2) {
    const int idx = blockIdx.x * 256 + threadIdx.x;
    const int b = idx >> 10, q = idx & 1023;
    const float* gi = g_gi + b * 3072;
    const float* gh = g_gh + b * 3072;
    float ir = gi[q], iz = gi[q + 1024], in_ = gi[q + 2048];
    float hr = gh[q], hz = gh[q + 1024], hn = gh[q + 2048];
    float r = 1.f / (1.f + __expf(-(ir + hr)));
    float z = 1.f / (1.f + __expf(-(iz + hz)));
    float n = tanhf(in_ + r * hn);
    float h = (1.f - z) * n + z * hprev[idx];
    out1[idx] = h;
    if (out2) out2[idx] = h;
}

// ---------------- launch ----------------
extern "C" void kernel_launch(void* const* d_in, const int* in_sizes, int n_in,
                              void* d_out, int out_size) {
    const int*   cur    = (const int*)d_in[0];
    const float* state  = (const float*)d_in[1];
    const float* enc    = (const float*)d_in[2];
    const float* emb    = (const float*)d_in[3];
    const float* w_att1 = (const float*)d_in[4];
    const float* w_att2 = (const float*)d_in[5];
    const float* w_ih0  = (const float*)d_in[6];
    const float* w_hh0  = (const float*)d_in[7];
    const float* b_ih0  = (const float*)d_in[8];
    const float* b_hh0  = (const float*)d_in[9];
    const float* w_ih1  = (const float*)d_in[10];
    const float* w_hh1  = (const float*)d_in[11];
    const float* b_ih1  = (const float*)d_in[12];
    const float* b_hh1  = (const float*)d_in[13];
    const float* w_out  = (const float*)d_in[14];
    const float* b_out  = (const float*)d_in[15];

    float* out = (float*)d_out;
    float* st0 = out + (size_t)BATCH * VOCAB;
    float* st1 = st0 + BATCH * HID;

    float *p_dproj, *p_x, *p_gi, *p_gh, *p_h0;
    cudaGetSymbolAddress((void**)&p_dproj, g_dproj);
    cudaGetSymbolAddress((void**)&p_x,     g_x);
    cudaGetSymbolAddress((void**)&p_gi,    g_gi);
    cudaGetSymbolAddress((void**)&p_gh,    g_gh);
    cudaGetSymbolAddress((void**)&p_h0,    g_h0);

    cudaFuncSetAttribute(attn_mma, cudaFuncAttributeMaxDynamicSharedMemorySize,
                         SMEM_TOTAL_ATT);

    const float* dec = state + (size_t)BATCH * HID;

    // 0. prep: split weights; enc -> fp16 hi
    prep_b<<<dim3(32, 32), dim3(32, 8)>>>(w_att1);
    prep_enc<<<(MAXLEN * BATCH * HID) / (256 * 4), 256>>>(enc);
    // 1. dproj = dec @ w1_d
    gemm64<false><<<16, 256>>>(dec, w_att1 + (size_t)HID * HID, nullptr,
                               p_dproj, HID, HID, HID);
    // 2. attention energies: 2-pass fp16 tensor-core GEMM + fused tanh/project
    attn_mma<<<dim3(NCHUNK, 512), 512, SMEM_TOTAL_ATT>>>(w_att2);
    // 3. softmax over time
    softmax_kernel<<<BATCH, 256>>>();
    // 4. context vector
    context_kernel<<<dim3(BATCH, 8), 1024>>>(enc);
    // 5. x = concat(emb, c)
    build_x<<<BATCH, 512>>>(cur, emb);
    // 6. GRU layer 0
    gemm64<true><<<48, 256>>>(p_x,   w_ih0, b_ih0, p_gi, 3 * HID, EMBED + HID, 3 * HID);
    gemm64<true><<<48, 256>>>(state, w_hh0, b_hh0, p_gh, 3 * HID, HID,         3 * HID);
    gru_gates<<<256, 256>>>(state, st0, p_h0);
    // 7. GRU layer 1
    gemm64<true><<<48, 256>>>(p_h0, w_ih1, b_ih1, p_gi, 3 * HID, HID, 3 * HID);
    gemm64<true><<<48, 256>>>(dec,  w_hh1, b_hh1, p_gh, 3 * HID, HID, 3 * HID);
    gru_gates<<<256, 256>>>(dec, st1, nullptr);
    // 8. logits
    gemm64<true><<<(VOCAB + 63) / 64, 256>>>(st1, w_out, b_out, out, VOCAB, HID, VOCAB);
}

// round 8
// speedup vs baseline: 1.7270x; 1.3167x over previous
#include <cuda_runtime.h>
#include <cuda_fp16.h>
#include <cstdint>
#include <cstddef>

#define HID    1024
#define EMBED  512
#define BATCH  64
#define MAXLEN 1024
#define VOCAB  50257
#define NCHUNK 8            // 1024 attn dims / 128 per block

// ---------------- scratch (no allocations allowed) ----------------
__device__ float  g_dproj[BATCH * HID];
__device__ float  g_epart[NCHUNK * MAXLEN * BATCH];
__device__ float  g_alpha[MAXLEN * BATCH];
__device__ float  g_cpart[8 * BATCH * HID];
__device__ float  g_x[BATCH * (EMBED + HID)];
__device__ float  g_gi[BATCH * 3 * HID];
__device__ float  g_gh[BATCH * 3 * HID];
__device__ float  g_h0[BATCH * HID];
__device__ __half g_bh[HID * HID];                     // w1e^T fp16 [n][k]
__device__ __half g_eh[(size_t)MAXLEN * BATCH * HID];  // enc fp16
__device__ __half g_wh[(size_t)VOCAB * HID];           // w_out fp16 [n][k]
__device__ __half g_h1h[BATCH * HID];                  // h1 fp16-hi
__device__ __half g_h1l[BATCH * HID];                  // h1 fp16-lo

// ---------------- prep: transpose + fp16 w1e ----------------
__global__ void prep_b(const float* __restrict__ w1e) {
    __shared__ float tile[32][33];
    int k0 = blockIdx.x * 32, n0 = blockIdx.y * 32;
    int tx = threadIdx.x, ty = threadIdx.y;
    for (int i = ty; i < 32; i += 8)
        tile[i][tx] = w1e[(size_t)(k0 + i) * HID + n0 + tx];
    __syncthreads();
    for (int i = ty; i < 32; i += 8)
        g_bh[(size_t)(n0 + i) * HID + k0 + tx] = __float2half_rn(tile[tx][i]);
}

// ---------------- prep: fp16 enc_states ----------------
__global__ void prep_enc(const float* __restrict__ enc) {
    size_t i = ((size_t)blockIdx.x * 256 + threadIdx.x) * 4;
    float4 v = *(const float4*)(enc + i);
    __half h[4];
    h[0] = __float2half_rn(v.x);
    h[1] = __float2half_rn(v.y);
    h[2] = __float2half_rn(v.z);
    h[3] = __float2half_rn(v.w);
    *(uint2*)(g_eh + i) = *(uint2*)h;
}

// ---------------- prep: fp16 w_out ----------------
__global__ void prep_wout(const float* __restrict__ w) {
    size_t i = ((size_t)blockIdx.x * 256 + threadIdx.x) * 4;
    if (i + 3 >= (size_t)VOCAB * HID) return;
    float4 v = *(const float4*)(w + i);
    __half h[4];
    h[0] = __float2half_rn(v.x);
    h[1] = __float2half_rn(v.y);
    h[2] = __float2half_rn(v.z);
    h[3] = __float2half_rn(v.w);
    *(uint2*)(g_wh + i) = *(uint2*)h;
}

// ---------------- prep: split h1 into hi/lo fp16 ----------------
__global__ void split_h1(const float* __restrict__ h1) {
    int i = (blockIdx.x * 256 + threadIdx.x) * 4;
    float4 v = *(const float4*)(h1 + i);
    float x[4] = {v.x, v.y, v.z, v.w};
    __half hh[4], hl[4];
    #pragma unroll
    for (int e = 0; e < 4; e++) {
        hh[e] = __float2half_rn(x[e]);
        hl[e] = __float2half_rn(x[e] - __half2float(hh[e]));
    }
    *(uint2*)(g_h1h + i) = *(uint2*)hh;
    *(uint2*)(g_h1l + i) = *(uint2*)hl;
}

// ---------------- helpers ----------------
__device__ __forceinline__ uint32_t smem_u32(const void* p) {
    uint32_t a;
    asm("{ .reg .u64 t; cvta.to.shared.u64 t, %1; cvt.u32.u64 %0, t; }" : "=r"(a) : "l"(p));
    return a;
}
__device__ __forceinline__ void cp16(void* s, const void* g) {
    asm volatile("cp.async.cg.shared.global [%0], [%1], 16;"
                 :: "r"(smem_u32(s)), "l"(g));
}
__device__ __forceinline__ void cp_commit() {
    asm volatile("cp.async.commit_group;" ::: "memory");
}
template <int N>
__device__ __forceinline__ void cp_wait() {
    asm volatile("cp.async.wait_group %0;" :: "n"(N) : "memory");
}
__device__ __forceinline__ void mma16816(float* d, const uint32_t* a, const uint32_t* b) {
    asm volatile("mma.sync.aligned.m16n8k16.row.col.f32.f16.f16.f32 "
                 "{%0,%1,%2,%3}, {%4,%5,%6,%7}, {%8,%9}, {%0,%1,%2,%3};"
                 : "+f"(d[0]), "+f"(d[1]), "+f"(d[2]), "+f"(d[3])
                 : "r"(a[0]), "r"(a[1]), "r"(a[2]), "r"(a[3]),
                   "r"(b[0]), "r"(b[1]));
}
__device__ __forceinline__ void ldsm4(uint32_t* r, uint32_t addr) {
    asm volatile("ldmatrix.sync.aligned.m8n8.x4.shared.b16 {%0,%1,%2,%3}, [%4];"
                 : "=r"(r[0]), "=r"(r[1]), "=r"(r[2]), "=r"(r[3]) : "r"(addr));
}

// ================= attention GEMM: single-pass fp16, ldmatrix, 4-stage =================
// block 128 rows x 128 attn dims, K=1024 in 64-chunks. warp tile 32x32.
#define ASTRIDE 72
#define MATH (128 * ASTRIDE)          // halves per tile
#define STAGE_BYTES (2 * MATH * 2)    // sAh sBh = 36864 B
#define NSTAGE 4
#define SMEM_TOTAL_ATT (NSTAGE * STAGE_BYTES)   // 147456 B
#define KC 64
#define KT (HID / KC)                 // 16

__global__ void __launch_bounds__(512, 1)
attn_mma(const float* __restrict__ w2) {
    extern __shared__ char smem[];
    const uint32_t sbase = smem_u32(smem);
    const int bn = blockIdx.x;       // n-chunk
    const int mt = blockIdx.y;       // row tile
    const int tid = threadIdx.x;
    const int wid = tid >> 5, lane = tid & 31;
    const int wm = wid >> 2, wn = wid & 3;     // warps: 4(M) x 4(N)
    const int qr = lane >> 2, qc = lane & 3;

    const __half* gAh = g_eh + (size_t)mt * 128 * HID;
    const __half* gBh = g_bh + (size_t)(bn * 128) * HID;

    const int lr = tid >> 2, lc = tid & 3;

    auto issue_load = [&](int kt) {
        char* base = smem + (kt % NSTAGE) * STAGE_BYTES;
        __half* sAh = (__half*)base;
        __half* sBh = sAh + MATH;
        #pragma unroll
        for (int i = 0; i < 2; i++) {
            int c = lc + i * 4;
            size_t go = (size_t)lr * HID + kt * KC + c * 8;
            int so = lr * ASTRIDE + c * 8;
            cp16(sAh + so, gAh + go);
            cp16(sBh + so, gBh + go);
        }
        cp_commit();
    };

    int offA[2];
    #pragma unroll
    for (int m = 0; m < 2; m++)
        offA[m] = ((wm * 32 + m * 16 + (lane & 15)) * ASTRIDE + (lane >> 4) * 8) * 2;
    int offB[2];
    #pragma unroll
    for (int j = 0; j < 2; j++)
        offB[j] = ((wn * 32 + (2 * j + (lane >> 4)) * 8 + (lane & 7)) * ASTRIDE
                   + ((lane >> 3) & 1) * 8) * 2;

    float acc[2][4][4] = {};

    auto compute = [&](int kt) {
        const uint32_t base = sbase + (kt % NSTAGE) * STAGE_BYTES;
        const uint32_t uAh = base;
        const uint32_t uBh = base + MATH * 2;
        #pragma unroll
        for (int ks = 0; ks < KC; ks += 16) {
            uint32_t ah[2][4], bh[4][2];
            #pragma unroll
            for (int m = 0; m < 2; m++)
                ldsm4(ah[m], uAh + offA[m] + ks * 2);
            #pragma unroll
            for (int j = 0; j < 2; j++) {
                uint32_t r[4];
                ldsm4(r, uBh + offB[j] + ks * 2);
                bh[2 * j][0] = r[0]; bh[2 * j][1] = r[1];
                bh[2 * j + 1][0] = r[2]; bh[2 * j + 1][1] = r[3];
            }
            #pragma unroll
            for (int m = 0; m < 2; m++)
                #pragma unroll
                for (int n = 0; n < 4; n++) mma16816(acc[m][n], ah[m], bh[n]);
        }
    };

    issue_load(0);
    issue_load(1);
    issue_load(2);
    for (int kt = 0; kt < KT; kt++) {
        cp_wait<2>();
        __syncthreads();
        if (kt + 3 < KT) issue_load(kt + 3);
        else cp_commit();
        compute(kt);
    }

    // epilogue: e_partial[row] = sum_n tanh(acc + dproj[b][n]) * w2[n]
    float rsum[2][2] = {};
    #pragma unroll
    for (int m = 0; m < 2; m++) {
        #pragma unroll
        for (int n = 0; n < 4; n++) {
            int ng0 = bn * 128 + wn * 32 + n * 8 + qc * 2;
            float w20 = w2[ng0], w21 = w2[ng0 + 1];
            #pragma unroll
            for (int pr = 0; pr < 2; pr++) {
                int row_local = wm * 32 + m * 16 + qr + pr * 8;
                int b = row_local & 63;
                const float* dp = g_dproj + (size_t)b * HID + ng0;
                rsum[m][pr] += tanhf(acc[m][n][pr * 2 + 0] + dp[0]) * w20
                             + tanhf(acc[m][n][pr * 2 + 1] + dp[1]) * w21;
            }
        }
    }
    #pragma unroll
    for (int m = 0; m < 2; m++)
        #pragma unroll
        for (int pr = 0; pr < 2; pr++) {
            float v = rsum[m][pr];
            v += __shfl_xor_sync(0xffffffffu, v, 1);
            v += __shfl_xor_sync(0xffffffffu, v, 2);
            rsum[m][pr] = v;
        }
    float* part = (float*)smem;
    __syncthreads();
    if (qc == 0) {
        #pragma unroll
        for (int m = 0; m < 2; m++)
            #pragma unroll
            for (int pr = 0; pr < 2; pr++)
                part[(wm * 32 + m * 16 + qr + pr * 8) * 4 + wn] = rsum[m][pr];
    }
    __syncthreads();
    if (tid < 128) {
        float e = part[tid * 4 + 0] + part[tid * 4 + 1] + part[tid * 4 + 2] + part[tid * 4 + 3];
        g_epart[(size_t)bn * (MAXLEN * BATCH) + mt * 128 + tid] = e;
    }
}

// ================= logits GEMM: 64 x VOCAB, A=h1 (hi/lo 2-pass), B=w_out fp16 =================
// block 64 rows x 128 vocab cols, 256 threads, warps 2(M) x 4(N), warp tile 32x32.
#define L_ASTR 72
#define L_MA (64 * L_ASTR)            // A tile halves
#define L_MB (128 * L_ASTR)           // B tile halves
#define L_STAGE ((2 * L_MA + L_MB) * 2)   // sAh sAl sB = 36864 B
#define L_NSTAGE 4
#define SMEM_TOTAL_LOG (L_NSTAGE * L_STAGE)

__global__ void __launch_bounds__(256, 1)
logits_mma(const float* __restrict__ bias, float* __restrict__ out) {
    extern __shared__ char smem[];
    const uint32_t sbase = smem_u32(smem);
    const int n0 = blockIdx.x * 128;
    const int tid = threadIdx.x;
    const int wid = tid >> 5, lane = tid & 31;
    const int wm = wid >> 2, wn = wid & 3;     // 2(M) x 4(N)
    const int qr = lane >> 2, qc = lane & 3;

    // loaders
    const int ar = tid >> 2, ac = tid & 3;     // A: 64 rows x chunks {ac, ac+4}
    const int br = tid >> 1, bc0 = (tid & 1) * 4;  // B: 128 rows x 4 chunks

    auto issue_load = [&](int kt) {
        char* base = smem + (kt % L_NSTAGE) * L_STAGE;
        __half* sAh = (__half*)base;
        __half* sAl = sAh + L_MA;
        __half* sB  = sAl + L_MA;
        #pragma unroll
        for (int i = 0; i < 2; i++) {
            int c = ac + i * 4;
            size_t go = (size_t)ar * HID + kt * KC + c * 8;
            int so = ar * L_ASTR + c * 8;
            cp16(sAh + so, g_h1h + go);
            cp16(sAl + so, g_h1l + go);
        }
        int gn = n0 + br; if (gn >= VOCAB) gn = VOCAB - 1;
        #pragma unroll
        for (int i = 0; i < 4; i++) {
            int c = bc0 + i;
            cp16(sB + br * L_ASTR + c * 8, g_wh + (size_t)gn * HID + kt * KC + c * 8);
        }
        cp_commit();
    };

    int offA[2];
    #pragma unroll
    for (int m = 0; m < 2; m++)
        offA[m] = ((wm * 32 + m * 16 + (lane & 15)) * L_ASTR + (lane >> 4) * 8) * 2;
    int offB[2];
    #pragma unroll
    for (int j = 0; j < 2; j++)
        offB[j] = ((wn * 32 + (2 * j + (lane >> 4)) * 8 + (lane & 7)) * L_ASTR
                   + ((lane >> 3) & 1) * 8) * 2;

    float acc[2][4][4] = {};

    auto compute = [&](int kt) {
        const uint32_t base = sbase + (kt % L_NSTAGE) * L_STAGE;
        const uint32_t uAh = base;
        const uint32_t uAl = base + L_MA * 2;
        const uint32_t uB  = base + 2 * L_MA * 2;
        #pragma unroll
        for (int ks = 0; ks < KC; ks += 16) {
            uint32_t ah[2][4], al[2][4], bb[4][2];
            #pragma unroll
            for (int m = 0; m < 2; m++) {
                ldsm4(ah[m], uAh + offA[m] + ks * 2);
                ldsm4(al[m], uAl + offA[m] + ks * 2);
            }
            #pragma unroll
            for (int j = 0; j < 2; j++) {
                uint32_t r[4];
                ldsm4(r, uB + offB[j] + ks * 2);
                bb[2 * j][0] = r[0]; bb[2 * j][1] = r[1];
                bb[2 * j + 1][0] = r[2]; bb[2 * j + 1][1] = r[3];
            }
            #pragma unroll
            for (int m = 0; m < 2; m++)
                #pragma unroll
                for (int n = 0; n < 4; n++) mma16816(acc[m][n], ah[m], bb[n]);
            #pragma unroll
            for (int m = 0; m < 2; m++)
                #pragma unroll
                for (int n = 0; n < 4; n++) mma16816(acc[m][n], al[m], bb[n]);
        }
    };

    issue_load(0);
    issue_load(1);
    issue_load(2);
    for (int kt = 0; kt < KT; kt++) {
        cp_wait<2>();
        __syncthreads();
        if (kt + 3 < KT) issue_load(kt + 3);
        else cp_commit();
        compute(kt);
    }

    // epilogue: out[row][n] = acc + bias[n]
    #pragma unroll
    for (int m = 0; m < 2; m++) {
        #pragma unroll
        for (int n = 0; n < 4; n++) {
            int col = n0 + wn * 32 + n * 8 + qc * 2;
            #pragma unroll
            for (int pr = 0; pr < 2; pr++) {
                int row = wm * 32 + m * 16 + qr + pr * 8;
                if (col < VOCAB)
                    out[(size_t)row * VOCAB + col] = acc[m][n][pr * 2 + 0] + bias[col];
                if (col + 1 < VOCAB)
                    out[(size_t)row * VOCAB + col + 1] = acc[m][n][pr * 2 + 1] + bias[col + 1];
            }
        }
    }
}

// ---------------- generic M=64 GEMM (fp32) ----------------
template <bool BT>
__global__ void gemm64(const float* __restrict__ A, const float* __restrict__ B,
                       const float* __restrict__ bias, float* __restrict__ C,
                       int N, int K, int ldc) {
    __shared__ float As[64][16];
    __shared__ float Bs[16][64];
    const int nT  = blockIdx.x * 64;
    const int tid = threadIdx.x;
    const int tx  = tid & 15, ty = tid >> 4;
    const int m4  = tid >> 2, kq = tid & 3;

    float acc[4][4] = {};
    for (int k0 = 0; k0 < K; k0 += 16) {
        float4 avv = *(const float4*)(A + (size_t)m4 * K + k0 + kq * 4);
        *(float4*)&As[m4][kq * 4] = avv;
        if (BT) {
            int n = tid >> 2;
            int gn = nT + n;
            float4 bv = make_float4(0.f, 0.f, 0.f, 0.f);
            if (gn < N) bv = *(const float4*)(B + (size_t)gn * K + k0 + kq * 4);
            Bs[kq * 4 + 0][n] = bv.x;
            Bs[kq * 4 + 1][n] = bv.y;
            Bs[kq * 4 + 2][n] = bv.z;
            Bs[kq * 4 + 3][n] = bv.w;
        } else {
            #pragma unroll
            for (int e2 = 0; e2 < 4; e2++) {
                int lin = tid + e2 * 256;
                int kk = lin >> 6, n = lin & 63;
                int gn = nT + n;
                Bs[kk][n] = (gn < N) ? B[(size_t)(k0 + kk) * N + gn] : 0.f;
            }
        }
        __syncthreads();
        #pragma unroll
        for (int kk = 0; kk < 16; kk++) {
            float4 b4 = *(const float4*)&Bs[kk][tx * 4];
            float bj[4] = {b4.x, b4.y, b4.z, b4.w};
            #pragma unroll
            for (int i = 0; i < 4; i++) {
                float a = As[ty * 4 + i][kk];
                #pragma unroll
                for (int j = 0; j < 4; j++) acc[i][j] = fmaf(a, bj[j], acc[i][j]);
            }
        }
        __syncthreads();
    }
    #pragma unroll
    for (int i = 0; i < 4; i++) {
        int m = ty * 4 + i;
        #pragma unroll
        for (int j = 0; j < 4; j++) {
            int n = nT + tx * 4 + j;
            if (n < N) {
                float v = acc[i][j];
                if (bias) v += bias[n];
                C[(size_t)m * ldc + n] = v;
            }
        }
    }
}

// ---------------- softmax over t ----------------
__global__ void softmax_kernel() {
    const int b = blockIdx.x;
    __shared__ float es[MAXLEN];
    __shared__ float red[256];
    const int tid = threadIdx.x;

    float mx = -1e30f;
    for (int t = tid; t < MAXLEN; t += 256) {
        float s = 0.f;
        #pragma unroll
        for (int p = 0; p < NCHUNK; p++) s += g_epart[p * (MAXLEN * BATCH) + t * 64 + b];
        es[t] = s;
        mx = fmaxf(mx, s);
    }
    red[tid] = mx; __syncthreads();
    for (int s2 = 128; s2; s2 >>= 1) {
        if (tid < s2) red[tid] = fmaxf(red[tid], red[tid + s2]);
        __syncthreads();
    }
    mx = red[0]; __syncthreads();

    float sum = 0.f;
    for (int t = tid; t < MAXLEN; t += 256) {
        float v = __expf(es[t] - mx);
        es[t] = v;
        sum += v;
    }
    red[tid] = sum; __syncthreads();
    for (int s2 = 128; s2; s2 >>= 1) {
        if (tid < s2) red[tid] += red[tid + s2];
        __syncthreads();
    }
    float inv = 1.f / red[0];
    for (int t = tid; t < MAXLEN; t += 256) g_alpha[t * 64 + b] = es[t] * inv;
}

// ---------------- context ----------------
__global__ void context_kernel(const float* __restrict__ E) {
    const int b = blockIdx.x, seg = blockIdx.y;
    const int h = threadIdx.x;
    float acc = 0.f;
    #pragma unroll 4
    for (int t = seg * 128; t < (seg + 1) * 128; t++)
        acc = fmaf(g_alpha[t * 64 + b], E[((size_t)t * 64 + b) * HID + h], acc);
    g_cpart[(seg * BATCH + b) * HID + h] = acc;
}

// ---------------- x = concat(embedding[cur], c) ----------------
__global__ void build_x(const int* __restrict__ cur, const float* __restrict__ emb) {
    const int b = blockIdx.x, tid = threadIdx.x;
    const int tok = cur[b];
    for (int k = tid; k < EMBED; k += 512)
        g_x[b * (EMBED + HID) + k] = emb[(size_t)tok * EMBED + k];
    for (int k = tid; k < HID; k += 512) {
        float s = 0.f;
        #pragma unroll
        for (int p = 0; p < 8; p++) s += g_cpart[(p * BATCH + b) * HID + k];
        g_x[b * (EMBED + HID) + EMBED + k] = s;
    }
}

// ---------------- GRU gates ----------------
__global__ void gru_gates(const float* __restrict__ hprev,
                          float* __restrict__ out1, float* __restrict__ out2) {
    const int idx = blockIdx.x * 256 + threadIdx.x;
    const int b = idx >> 10, q = idx & 1023;
    const float* gi = g_gi + b * 3072;
    const float* gh = g_gh + b * 3072;
    float ir = gi[q], iz = gi[q + 1024], in_ = gi[q + 2048];
    float hr = gh[q], hz = gh[q + 1024], hn = gh[q + 2048];
    float r = 1.f / (1.f + __expf(-(ir + hr)));
    float z = 1.f / (1.f + __expf(-(iz + hz)));
    float n = tanhf(in_ + r * hn);
    float h = (1.f - z) * n + z * hprev[idx];
    out1[idx] = h;
    if (out2) out2[idx] = h;
}

// ---------------- launch ----------------
extern "C" void kernel_launch(void* const* d_in, const int* in_sizes, int n_in,
                              void* d_out, int out_size) {
    const int*   cur    = (const int*)d_in[0];
    const float* state  = (const float*)d_in[1];
    const float* enc    = (const float*)d_in[2];
    const float* emb    = (const float*)d_in[3];
    const float* w_att1 = (const float*)d_in[4];
    const float* w_att2 = (const float*)d_in[5];
    const float* w_ih0  = (const float*)d_in[6];
    const float* w_hh0  = (const float*)d_in[7];
    const float* b_ih0  = (const float*)d_in[8];
    const float* b_hh0  = (const float*)d_in[9];
    const float* w_ih1  = (const float*)d_in[10];
    const float* w_hh1  = (const float*)d_in[11];
    const float* b_ih1  = (const float*)d_in[12];
    const float* b_hh1  = (const float*)d_in[13];
    const float* w_out  = (const float*)d_in[14];
    const float* b_out  = (const float*)d_in[15];

    float* out = (float*)d_out;
    float* st0 = out + (size_t)BATCH * VOCAB;
    float* st1 = st0 + BATCH * HID;

    float *p_dproj, *p_x, *p_gi, *p_gh, *p_h0;
    cudaGetSymbolAddress((void**)&p_dproj, g_dproj);
    cudaGetSymbolAddress((void**)&p_x,     g_x);
    cudaGetSymbolAddress((void**)&p_gi,    g_gi);
    cudaGetSymbolAddress((void**)&p_gh,    g_gh);
    cudaGetSymbolAddress((void**)&p_h0,    g_h0);

    cudaFuncSetAttribute(attn_mma, cudaFuncAttributeMaxDynamicSharedMemorySize,
                         SMEM_TOTAL_ATT);
    cudaFuncSetAttribute(logits_mma, cudaFuncAttributeMaxDynamicSharedMemorySize,
                         SMEM_TOTAL_LOG);

    const float* dec = state + (size_t)BATCH * HID;

    // 0. prep
    prep_b<<<dim3(32, 32), dim3(32, 8)>>>(w_att1);
    prep_enc<<<(MAXLEN * BATCH * HID) / (256 * 4), 256>>>(enc);
    prep_wout<<<((int)(((size_t)VOCAB * HID) / 4) + 255) / 256, 256>>>(w_out);
    // 1. dproj = dec @ w1_d
    gemm64<false><<<16, 256>>>(dec, w_att1 + (size_t)HID * HID, nullptr,
                               p_dproj, HID, HID, HID);
    // 2. attention energies: single-pass fp16 tensor GEMM + fused tanh/project
    attn_mma<<<dim3(NCHUNK, 512), 512, SMEM_TOTAL_ATT>>>(w_att2);
    // 3. softmax
    softmax_kernel<<<BATCH, 256>>>();
    // 4. context
    context_kernel<<<dim3(BATCH, 8), 1024>>>(enc);
    // 5. x = concat(emb, c)
    build_x<<<BATCH, 512>>>(cur, emb);
    // 6. GRU layer 0
    gemm64<true><<<48, 256>>>(p_x,   w_ih0, b_ih0, p_gi, 3 * HID, EMBED + HID, 3 * HID);
    gemm64<true><<<48, 256>>>(state, w_hh0, b_hh0, p_gh, 3 * HID, HID,         3 * HID);
    gru_gates<<<256, 256>>>(state, st0, p_h0);
    // 7. GRU layer 1
    gemm64<true><<<48, 256>>>(p_h0, w_ih1, b_ih1, p_gi, 3 * HID, HID, 3 * HID);
    gemm64<true><<<48, 256>>>(dec,  w_hh1, b_hh1, p_gh, 3 * HID, HID, 3 * HID);
    gru_gates<<<256, 256>>>(dec, st1, nullptr);
    // 8. logits: fp16 2-pass tensor GEMM
    split_h1<<<BATCH, 256>>>(st1);
    logits_mma<<<(VOCAB + 127) / 128, 256, SMEM_TOTAL_LOG>>>(b_out, out);
}

// round 9
// speedup vs baseline: 2.2038x; 1.2761x over previous
#include <cuda_runtime.h>
#include <cuda_fp16.h>
#include <cstdint>
#include <cstddef>

#define HID    1024
#define EMBED  512
#define BATCH  64
#define MAXLEN 1024
#define VOCAB  50257
#define NCHUNK 8
#define KSPL   4

// ---------------- scratch (no allocations allowed) ----------------
__device__ float  g_dproj[BATCH * HID];
__device__ float  g_dp4[KSPL * BATCH * HID];
__device__ float  g_epart[NCHUNK * MAXLEN * BATCH];
__device__ float  g_alpha[MAXLEN * BATCH];
__device__ float  g_cpart[8 * BATCH * HID];
__device__ float  g_x[BATCH * (EMBED + HID)];
__device__ float  g_gi[KSPL * BATCH * 3 * HID];
__device__ float  g_gh[KSPL * BATCH * 3 * HID];
__device__ float  g_h0[BATCH * HID];
__device__ __half g_bh[HID * HID];                     // w1e^T fp16 [n][k]
__device__ __half g_eh[(size_t)MAXLEN * BATCH * HID];  // enc fp16
__device__ __half g_wh[(size_t)VOCAB * HID];           // w_out fp16 [n][k]
__device__ __half g_h1h[BATCH * HID];                  // h1 fp16-hi
__device__ __half g_h1l[BATCH * HID];                  // h1 fp16-lo

// ---------------- prep: transpose + fp16 w1e ----------------
__global__ void prep_b(const float* __restrict__ w1e) {
    __shared__ float tile[32][33];
    int k0 = blockIdx.x * 32, n0 = blockIdx.y * 32;
    int tx = threadIdx.x, ty = threadIdx.y;
    for (int i = ty; i < 32; i += 8)
        tile[i][tx] = w1e[(size_t)(k0 + i) * HID + n0 + tx];
    __syncthreads();
    for (int i = ty; i < 32; i += 8)
        g_bh[(size_t)(n0 + i) * HID + k0 + tx] = __float2half_rn(tile[tx][i]);
}

// ---------------- prep: fp16 enc_states ----------------
__global__ void prep_enc(const float* __restrict__ enc) {
    size_t i = ((size_t)blockIdx.x * 256 + threadIdx.x) * 4;
    float4 v = *(const float4*)(enc + i);
    __half h[4];
    h[0] = __float2half_rn(v.x);
    h[1] = __float2half_rn(v.y);
    h[2] = __float2half_rn(v.z);
    h[3] = __float2half_rn(v.w);
    *(uint2*)(g_eh + i) = *(uint2*)h;
}

// ---------------- prep: fp16 w_out ----------------
__global__ void prep_wout(const float* __restrict__ w) {
    size_t i = ((size_t)blockIdx.x * 256 + threadIdx.x) * 4;
    if (i + 3 >= (size_t)VOCAB * HID) return;
    float4 v = *(const float4*)(w + i);
    __half h[4];
    h[0] = __float2half_rn(v.x);
    h[1] = __float2half_rn(v.y);
    h[2] = __float2half_rn(v.z);
    h[3] = __float2half_rn(v.w);
    *(uint2*)(g_wh + i) = *(uint2*)h;
}

// ---------------- prep: split h1 into hi/lo fp16 ----------------
__global__ void split_h1(const float* __restrict__ h1) {
    int i = (blockIdx.x * 256 + threadIdx.x) * 4;
    float4 v = *(const float4*)(h1 + i);
    float x[4] = {v.x, v.y, v.z, v.w};
    __half hh[4], hl[4];
    #pragma unroll
    for (int e = 0; e < 4; e++) {
        hh[e] = __float2half_rn(x[e]);
        hl[e] = __float2half_rn(x[e] - __half2float(hh[e]));
    }
    *(uint2*)(g_h1h + i) = *(uint2*)hh;
    *(uint2*)(g_h1l + i) = *(uint2*)hl;
}

// ---------------- helpers ----------------
__device__ __forceinline__ uint32_t smem_u32(const void* p) {
    uint32_t a;
    asm("{ .reg .u64 t; cvta.to.shared.u64 t, %1; cvt.u32.u64 %0, t; }" : "=r"(a) : "l"(p));
    return a;
}
__device__ __forceinline__ void cp16(void* s, const void* g) {
    asm volatile("cp.async.cg.shared.global [%0], [%1], 16;"
                 :: "r"(smem_u32(s)), "l"(g));
}
__device__ __forceinline__ void cp_commit() {
    asm volatile("cp.async.commit_group;" ::: "memory");
}
template <int N>
__device__ __forceinline__ void cp_wait() {
    asm volatile("cp.async.wait_group %0;" :: "n"(N) : "memory");
}
__device__ __forceinline__ void mma16816(float* d, const uint32_t* a, const uint32_t* b) {
    asm volatile("mma.sync.aligned.m16n8k16.row.col.f32.f16.f16.f32 "
                 "{%0,%1,%2,%3}, {%4,%5,%6,%7}, {%8,%9}, {%0,%1,%2,%3};"
                 : "+f"(d[0]), "+f"(d[1]), "+f"(d[2]), "+f"(d[3])
                 : "r"(a[0]), "r"(a[1]), "r"(a[2]), "r"(a[3]),
                   "r"(b[0]), "r"(b[1]));
}
__device__ __forceinline__ void ldsm4(uint32_t* r, uint32_t addr) {
    asm volatile("ldmatrix.sync.aligned.m8n8.x4.shared.b16 {%0,%1,%2,%3}, [%4];"
                 : "=r"(r[0]), "=r"(r[1]), "=r"(r[2]), "=r"(r[3]) : "r"(addr));
}

// ================= attention GEMM: single-pass fp16, ldmatrix, 4-stage =================
#define ASTRIDE 72
#define MATH (128 * ASTRIDE)
#define STAGE_BYTES (2 * MATH * 2)
#define NSTAGE 4
#define SMEM_TOTAL_ATT (NSTAGE * STAGE_BYTES)
#define KC 64
#define KT (HID / KC)

__global__ void __launch_bounds__(512, 1)
attn_mma(const float* __restrict__ w2) {
    extern __shared__ char smem[];
    const uint32_t sbase = smem_u32(smem);
    const int bn = blockIdx.x;
    const int mt = blockIdx.y;
    const int tid = threadIdx.x;
    const int wid = tid >> 5, lane = tid & 31;
    const int wm = wid >> 2, wn = wid & 3;
    const int qr = lane >> 2, qc = lane & 3;

    const __half* gAh = g_eh + (size_t)mt * 128 * HID;
    const __half* gBh = g_bh + (size_t)(bn * 128) * HID;

    const int lr = tid >> 2, lc = tid & 3;

    auto issue_load = [&](int kt) {
        char* base = smem + (kt % NSTAGE) * STAGE_BYTES;
        __half* sAh = (__half*)base;
        __half* sBh = sAh + MATH;
        #pragma unroll
        for (int i = 0; i < 2; i++) {
            int c = lc + i * 4;
            size_t go = (size_t)lr * HID + kt * KC + c * 8;
            int so = lr * ASTRIDE + c * 8;
            cp16(sAh + so, gAh + go);
            cp16(sBh + so, gBh + go);
        }
        cp_commit();
    };

    int offA[2];
    #pragma unroll
    for (int m = 0; m < 2; m++)
        offA[m] = ((wm * 32 + m * 16 + (lane & 15)) * ASTRIDE + (lane >> 4) * 8) * 2;
    int offB[2];
    #pragma unroll
    for (int j = 0; j < 2; j++)
        offB[j] = ((wn * 32 + (2 * j + (lane >> 4)) * 8 + (lane & 7)) * ASTRIDE
                   + ((lane >> 3) & 1) * 8) * 2;

    float acc[2][4][4] = {};

    auto compute = [&](int kt) {
        const uint32_t base = sbase + (kt % NSTAGE) * STAGE_BYTES;
        const uint32_t uAh = base;
        const uint32_t uBh = base + MATH * 2;
        #pragma unroll
        for (int ks = 0; ks < KC; ks += 16) {
            uint32_t ah[2][4], bh[4][2];
            #pragma unroll
            for (int m = 0; m < 2; m++)
                ldsm4(ah[m], uAh + offA[m] + ks * 2);
            #pragma unroll
            for (int j = 0; j < 2; j++) {
                uint32_t r[4];
                ldsm4(r, uBh + offB[j] + ks * 2);
                bh[2 * j][0] = r[0]; bh[2 * j][1] = r[1];
                bh[2 * j + 1][0] = r[2]; bh[2 * j + 1][1] = r[3];
            }
            #pragma unroll
            for (int m = 0; m < 2; m++)
                #pragma unroll
                for (int n = 0; n < 4; n++) mma16816(acc[m][n], ah[m], bh[n]);
        }
    };

    issue_load(0);
    issue_load(1);
    issue_load(2);
    for (int kt = 0; kt < KT; kt++) {
        cp_wait<2>();
        __syncthreads();
        if (kt + 3 < KT) issue_load(kt + 3);
        else cp_commit();
        compute(kt);
    }

    float rsum[2][2] = {};
    #pragma unroll
    for (int m = 0; m < 2; m++) {
        #pragma unroll
        for (int n = 0; n < 4; n++) {
            int ng0 = bn * 128 + wn * 32 + n * 8 + qc * 2;
            float w20 = w2[ng0], w21 = w2[ng0 + 1];
            #pragma unroll
            for (int pr = 0; pr < 2; pr++) {
                int row_local = wm * 32 + m * 16 + qr + pr * 8;
                int b = row_local & 63;
                const float* dp = g_dproj + (size_t)b * HID + ng0;
                rsum[m][pr] += tanhf(acc[m][n][pr * 2 + 0] + dp[0]) * w20
                             + tanhf(acc[m][n][pr * 2 + 1] + dp[1]) * w21;
            }
        }
    }
    #pragma unroll
    for (int m = 0; m < 2; m++)
        #pragma unroll
        for (int pr = 0; pr < 2; pr++) {
            float v = rsum[m][pr];
            v += __shfl_xor_sync(0xffffffffu, v, 1);
            v += __shfl_xor_sync(0xffffffffu, v, 2);
            rsum[m][pr] = v;
        }
    float* part = (float*)smem;
    __syncthreads();
    if (qc == 0) {
        #pragma unroll
        for (int m = 0; m < 2; m++)
            #pragma unroll
            for (int pr = 0; pr < 2; pr++)
                part[(wm * 32 + m * 16 + qr + pr * 8) * 4 + wn] = rsum[m][pr];
    }
    __syncthreads();
    if (tid < 128) {
        float e = part[tid * 4 + 0] + part[tid * 4 + 1] + part[tid * 4 + 2] + part[tid * 4 + 3];
        g_epart[(size_t)bn * (MAXLEN * BATCH) + mt * 128 + tid] = e;
    }
}

// ================= logits GEMM =================
#define L_ASTR 72
#define L_MA (64 * L_ASTR)
#define L_MB (128 * L_ASTR)
#define L_STAGE ((2 * L_MA + L_MB) * 2)
#define L_NSTAGE 4
#define SMEM_TOTAL_LOG (L_NSTAGE * L_STAGE)

__global__ void __launch_bounds__(256, 1)
logits_mma(const float* __restrict__ bias, float* __restrict__ out) {
    extern __shared__ char smem[];
    const uint32_t sbase = smem_u32(smem);
    const int n0 = blockIdx.x * 128;
    const int tid = threadIdx.x;
    const int wid = tid >> 5, lane = tid & 31;
    const int wm = wid >> 2, wn = wid & 3;
    const int qr = lane >> 2, qc = lane & 3;

    const int ar = tid >> 2, ac = tid & 3;
    const int br = tid >> 1, bc0 = (tid & 1) * 4;

    auto issue_load = [&](int kt) {
        char* base = smem + (kt % L_NSTAGE) * L_STAGE;
        __half* sAh = (__half*)base;
        __half* sAl = sAh + L_MA;
        __half* sB  = sAl + L_MA;
        #pragma unroll
        for (int i = 0; i < 2; i++) {
            int c = ac + i * 4;
            size_t go = (size_t)ar * HID + kt * KC + c * 8;
            int so = ar * L_ASTR + c * 8;
            cp16(sAh + so, g_h1h + go);
            cp16(sAl + so, g_h1l + go);
        }
        int gn = n0 + br; if (gn >= VOCAB) gn = VOCAB - 1;
        #pragma unroll
        for (int i = 0; i < 4; i++) {
            int c = bc0 + i;
            cp16(sB + br * L_ASTR + c * 8, g_wh + (size_t)gn * HID + kt * KC + c * 8);
        }
        cp_commit();
    };

    int offA[2];
    #pragma unroll
    for (int m = 0; m < 2; m++)
        offA[m] = ((wm * 32 + m * 16 + (lane & 15)) * L_ASTR + (lane >> 4) * 8) * 2;
    int offB[2];
    #pragma unroll
    for (int j = 0; j < 2; j++)
        offB[j] = ((wn * 32 + (2 * j + (lane >> 4)) * 8 + (lane & 7)) * L_ASTR
                   + ((lane >> 3) & 1) * 8) * 2;

    float acc[2][4][4] = {};

    auto compute = [&](int kt) {
        const uint32_t base = sbase + (kt % L_NSTAGE) * L_STAGE;
        const uint32_t uAh = base;
        const uint32_t uAl = base + L_MA * 2;
        const uint32_t uB  = base + 2 * L_MA * 2;
        #pragma unroll
        for (int ks = 0; ks < KC; ks += 16) {
            uint32_t ah[2][4], al[2][4], bb[4][2];
            #pragma unroll
            for (int m = 0; m < 2; m++) {
                ldsm4(ah[m], uAh + offA[m] + ks * 2);
                ldsm4(al[m], uAl + offA[m] + ks * 2);
            }
            #pragma unroll
            for (int j = 0; j < 2; j++) {
                uint32_t r[4];
                ldsm4(r, uB + offB[j] + ks * 2);
                bb[2 * j][0] = r[0]; bb[2 * j][1] = r[1];
                bb[2 * j + 1][0] = r[2]; bb[2 * j + 1][1] = r[3];
            }
            #pragma unroll
            for (int m = 0; m < 2; m++)
                #pragma unroll
                for (int n = 0; n < 4; n++) mma16816(acc[m][n], ah[m], bb[n]);
            #pragma unroll
            for (int m = 0; m < 2; m++)
                #pragma unroll
                for (int n = 0; n < 4; n++) mma16816(acc[m][n], al[m], bb[n]);
        }
    };

    issue_load(0);
    issue_load(1);
    issue_load(2);
    for (int kt = 0; kt < KT; kt++) {
        cp_wait<2>();
        __syncthreads();
        if (kt + 3 < KT) issue_load(kt + 3);
        else cp_commit();
        compute(kt);
    }

    #pragma unroll
    for (int m = 0; m < 2; m++) {
        #pragma unroll
        for (int n = 0; n < 4; n++) {
            int col = n0 + wn * 32 + n * 8 + qc * 2;
            #pragma unroll
            for (int pr = 0; pr < 2; pr++) {
                int row = wm * 32 + m * 16 + qr + pr * 8;
                if (col < VOCAB)
                    out[(size_t)row * VOCAB + col] = acc[m][n][pr * 2 + 0] + bias[col];
                if (col + 1 < VOCAB)
                    out[(size_t)row * VOCAB + col + 1] = acc[m][n][pr * 2 + 1] + bias[col + 1];
            }
        }
    }
}

// ---------------- K-split M=64 fp32 GEMM: partials to C[ks][64][ldc] ----------------
template <bool BT>
__global__ void gemm64_ks(const float* __restrict__ A, const float* __restrict__ B,
                          float* __restrict__ C, int N, int K, int ldc) {
    __shared__ float As[64][16];
    __shared__ float Bs[16][64];
    const int nT  = blockIdx.x * 64;
    const int ks  = blockIdx.y;
    const int Kseg = K / KSPL;
    A += ks * Kseg;                       // row stride is still K
    const float* Bp = BT ? (B + ks * Kseg) : (B + (size_t)ks * Kseg * N);
    C += (size_t)ks * 64 * ldc;
    const int tid = threadIdx.x;
    const int tx  = tid & 15, ty = tid >> 4;
    const int m4  = tid >> 2, kq = tid & 3;

    float acc[4][4] = {};
    for (int k0 = 0; k0 < Kseg; k0 += 16) {
        float4 avv = *(const float4*)(A + (size_t)m4 * K + k0 + kq * 4);
        *(float4*)&As[m4][kq * 4] = avv;
        if (BT) {
            int n = tid >> 2;
            int gn = nT + n;
            float4 bv = make_float4(0.f, 0.f, 0.f, 0.f);
            if (gn < N) bv = *(const float4*)(Bp + (size_t)gn * K + k0 + kq * 4);
            Bs[kq * 4 + 0][n] = bv.x;
            Bs[kq * 4 + 1][n] = bv.y;
            Bs[kq * 4 + 2][n] = bv.z;
            Bs[kq * 4 + 3][n] = bv.w;
        } else {
            #pragma unroll
            for (int e2 = 0; e2 < 4; e2++) {
                int lin = tid + e2 * 256;
                int kk = lin >> 6, n = lin & 63;
                int gn = nT + n;
                Bs[kk][n] = (gn < N) ? Bp[(size_t)(k0 + kk) * N + gn] : 0.f;
            }
        }
        __syncthreads();
        #pragma unroll
        for (int kk = 0; kk < 16; kk++) {
            float4 b4 = *(const float4*)&Bs[kk][tx * 4];
            float bj[4] = {b4.x, b4.y, b4.z, b4.w};
            #pragma unroll
            for (int i = 0; i < 4; i++) {
                float a = As[ty * 4 + i][kk];
                #pragma unroll
                for (int j = 0; j < 4; j++) acc[i][j] = fmaf(a, bj[j], acc[i][j]);
            }
        }
        __syncthreads();
    }
    #pragma unroll
    for (int i = 0; i < 4; i++) {
        int m = ty * 4 + i;
        #pragma unroll
        for (int j = 0; j < 4; j++) {
            int n = nT + tx * 4 + j;
            if (n < N) C[(size_t)m * ldc + n] = acc[i][j];
        }
    }
}

// ---------------- reduce dproj partials ----------------
__global__ void reduce_dproj() {
    int i = blockIdx.x * 256 + threadIdx.x;   // 65536
    float s = 0.f;
    #pragma unroll
    for (int p = 0; p < KSPL; p++) s += g_dp4[p * (BATCH * HID) + i];
    g_dproj[i] = s;
}

// ---------------- softmax over t ----------------
__global__ void softmax_kernel() {
    const int b = blockIdx.x;
    __shared__ float es[MAXLEN];
    __shared__ float red[256];
    const int tid = threadIdx.x;

    float mx = -1e30f;
    for (int t = tid; t < MAXLEN; t += 256) {
        float s = 0.f;
        #pragma unroll
        for (int p = 0; p < NCHUNK; p++) s += g_epart[p * (MAXLEN * BATCH) + t * 64 + b];
        es[t] = s;
        mx = fmaxf(mx, s);
    }
    red[tid] = mx; __syncthreads();
    for (int s2 = 128; s2; s2 >>= 1) {
        if (tid < s2) red[tid] = fmaxf(red[tid], red[tid + s2]);
        __syncthreads();
    }
    mx = red[0]; __syncthreads();

    float sum = 0.f;
    for (int t = tid; t < MAXLEN; t += 256) {
        float v = __expf(es[t] - mx);
        es[t] = v;
        sum += v;
    }
    red[tid] = sum; __syncthreads();
    for (int s2 = 128; s2; s2 >>= 1) {
        if (tid < s2) red[tid] += red[tid + s2];
        __syncthreads();
    }
    float inv = 1.f / red[0];
    for (int t = tid; t < MAXLEN; t += 256) g_alpha[t * 64 + b] = es[t] * inv;
}

// ---------------- context (fp16 enc) ----------------
__global__ void context_kernel() {
    const int b = blockIdx.x, seg = blockIdx.y;
    const int h = threadIdx.x;
    float acc = 0.f;
    #pragma unroll 4
    for (int t = seg * 128; t < (seg + 1) * 128; t++)
        acc = fmaf(g_alpha[t * 64 + b],
                   __half2float(g_eh[((size_t)t * 64 + b) * HID + h]), acc);
    g_cpart[(seg * BATCH + b) * HID + h] = acc;
}

// ---------------- x = concat(embedding[cur], c) ----------------
__global__ void build_x(const int* __restrict__ cur, const float* __restrict__ emb) {
    const int b = blockIdx.x, tid = threadIdx.x;
    const int tok = cur[b];
    for (int k = tid; k < EMBED; k += 512)
        g_x[b * (EMBED + HID) + k] = emb[(size_t)tok * EMBED + k];
    for (int k = tid; k < HID; k += 512) {
        float s = 0.f;
        #pragma unroll
        for (int p = 0; p < 8; p++) s += g_cpart[(p * BATCH + b) * HID + k];
        g_x[b * (EMBED + HID) + EMBED + k] = s;
    }
}

// ---------------- GRU gates (reduces K-split partials, adds biases) ----------------
__global__ void gru_gates(const float* __restrict__ hprev,
                          const float* __restrict__ b_ih,
                          const float* __restrict__ b_hh,
                          float* __restrict__ out1, float* __restrict__ out2) {
    const int idx = blockIdx.x * 256 + threadIdx.x;
    const int b = idx >> 10, q = idx & 1023;
    const int base = b * 3072 + q;
    float ir = b_ih[q], iz = b_ih[q + 1024], in_ = b_ih[q + 2048];
    float hr = b_hh[q], hz = b_hh[q + 1024], hn = b_hh[q + 2048];
    #pragma unroll
    for (int p = 0; p < KSPL; p++) {
        const float* gi = g_gi + p * (BATCH * 3 * HID);
        const float* gh = g_gh + p * (BATCH * 3 * HID);
        ir += gi[base];       hr += gh[base];
        iz += gi[base + 1024]; hz += gh[base + 1024];
        in_ += gi[base + 2048]; hn += gh[base + 2048];
    }
    float r = 1.f / (1.f + __expf(-(ir + hr)));
    float z = 1.f / (1.f + __expf(-(iz + hz)));
    float n = tanhf(in_ + r * hn);
    float h = (1.f - z) * n + z * hprev[idx];
    out1[idx] = h;
    if (out2) out2[idx] = h;
}

// ---------------- launch ----------------
extern "C" void kernel_launch(void* const* d_in, const int* in_sizes, int n_in,
                              void* d_out, int out_size) {
    const int*   cur    = (const int*)d_in[0];
    const float* state  = (const float*)d_in[1];
    const float* enc    = (const float*)d_in[2];
    const float* emb    = (const float*)d_in[3];
    const float* w_att1 = (const float*)d_in[4];
    const float* w_att2 = (const float*)d_in[5];
    const float* w_ih0  = (const float*)d_in[6];
    const float* w_hh0  = (const float*)d_in[7];
    const float* b_ih0  = (const float*)d_in[8];
    const float* b_hh0  = (const float*)d_in[9];
    const float* w_ih1  = (const float*)d_in[10];
    const float* w_hh1  = (const float*)d_in[11];
    const float* b_ih1  = (const float*)d_in[12];
    const float* b_hh1  = (const float*)d_in[13];
    const float* w_out  = (const float*)d_in[14];
    const float* b_out  = (const float*)d_in[15];

    float* out = (float*)d_out;
    float* st0 = out + (size_t)BATCH * VOCAB;
    float* st1 = st0 + BATCH * HID;

    float *p_dp4, *p_x, *p_gi, *p_gh, *p_h0;
    cudaGetSymbolAddress((void**)&p_dp4, g_dp4);
    cudaGetSymbolAddress((void**)&p_x,   g_x);
    cudaGetSymbolAddress((void**)&p_gi,  g_gi);
    cudaGetSymbolAddress((void**)&p_gh,  g_gh);
    cudaGetSymbolAddress((void**)&p_h0,  g_h0);

    cudaFuncSetAttribute(attn_mma, cudaFuncAttributeMaxDynamicSharedMemorySize,
                         SMEM_TOTAL_ATT);
    cudaFuncSetAttribute(logits_mma, cudaFuncAttributeMaxDynamicSharedMemorySize,
                         SMEM_TOTAL_LOG);

    const float* dec = state + (size_t)BATCH * HID;

    // 0. prep
    prep_b<<<dim3(32, 32), dim3(32, 8)>>>(w_att1);
    prep_enc<<<(MAXLEN * BATCH * HID) / (256 * 4), 256>>>(enc);
    prep_wout<<<((int)(((size_t)VOCAB * HID) / 4) + 255) / 256, 256>>>(w_out);
    // 1. dproj = dec @ w1_d  (K-split 4 + reduce)
    gemm64_ks<false><<<dim3(16, KSPL), 256>>>(dec, w_att1 + (size_t)HID * HID,
                                              p_dp4, HID, HID, HID);
    reduce_dproj<<<BATCH * HID / 256, 256>>>();
    // 2. attention energies
    attn_mma<<<dim3(NCHUNK, 512), 512, SMEM_TOTAL_ATT>>>(w_att2);
    // 3. softmax
    softmax_kernel<<<BATCH, 256>>>();
    // 4. context (fp16 enc)
    context_kernel<<<dim3(BATCH, 8), 1024>>>();
    // 5. x = concat(emb, c)
    build_x<<<BATCH, 512>>>(cur, emb);
    // 6. GRU layer 0 (K-split partials; gru_gates reduces + biases)
    gemm64_ks<true><<<dim3(48, KSPL), 256>>>(p_x,   w_ih0, p_gi, 3 * HID, EMBED + HID, 3 * HID);
    gemm64_ks<true><<<dim3(48, KSPL), 256>>>(state, w_hh0, p_gh, 3 * HID, HID,         3 * HID);
    gru_gates<<<256, 256>>>(state, b_ih0, b_hh0, st0, p_h0);
    // 7. GRU layer 1
    gemm64_ks<true><<<dim3(48, KSPL), 256>>>(p_h0, w_ih1, p_gi, 3 * HID, HID, 3 * HID);
    gemm64_ks<true><<<dim3(48, KSPL), 256>>>(dec,  w_hh1, p_gh, 3 * HID, HID, 3 * HID);
    gru_gates<<<256, 256>>>(dec, b_ih1, b_hh1, st1, nullptr);
    // 8. logits
    split_h1<<<BATCH, 256>>>(st1);
    logits_mma<<<(VOCAB + 127) / 128, 256, SMEM_TOTAL_LOG>>>(b_out, out);
}

// round 11
// speedup vs baseline: 2.2362x; 1.0147x over previous
#include <cuda_runtime.h>
#include <cuda_fp16.h>
#include <cstdint>
#include <cstddef>

#define HID    1024
#define EMBED  512
#define BATCH  64
#define MAXLEN 1024
#define VOCAB  50257
#define NCHUNK 8
#define KSPL   4
#define AUXY   64          // extra blockIdx.y rows in attn grid -> 64*8=512 aux blocks

// ---------------- scratch (no allocations allowed) ----------------
__device__ float  g_dproj[BATCH * HID];
__device__ float  g_dp4[KSPL * BATCH * HID];
__device__ float  g_epart[NCHUNK * MAXLEN * BATCH];
__device__ float  g_alpha[MAXLEN * BATCH];
__device__ float  g_cpart[8 * BATCH * HID];
__device__ float  g_x[BATCH * (EMBED + HID)];
__device__ float  g_gi[KSPL * BATCH * 3 * HID];
__device__ float  g_gh[KSPL * BATCH * 3 * HID];
__device__ float  g_h0[BATCH * HID];
__device__ __half g_bh[HID * HID];                     // w1e^T fp16 [n][k]
__device__ __half g_eh[(size_t)MAXLEN * BATCH * HID];  // enc fp16
__device__ __half g_wh[(size_t)VOCAB * HID];           // w_out fp16 [n][k]
__device__ __half g_h1h[BATCH * HID];                  // h1 fp16

// ---------------- prep: transpose + fp16 w1e ----------------
__global__ void prep_b(const float* __restrict__ w1e) {
    __shared__ float tile[32][33];
    int k0 = blockIdx.x * 32, n0 = blockIdx.y * 32;
    int tx = threadIdx.x, ty = threadIdx.y;
    for (int i = ty; i < 32; i += 8)
        tile[i][tx] = w1e[(size_t)(k0 + i) * HID + n0 + tx];
    __syncthreads();
    for (int i = ty; i < 32; i += 8)
        g_bh[(size_t)(n0 + i) * HID + k0 + tx] = __float2half_rn(tile[tx][i]);
}

// ---------------- prep: fp16 enc_states ----------------
__global__ void prep_enc(const float* __restrict__ enc) {
    size_t i = ((size_t)blockIdx.x * 256 + threadIdx.x) * 4;
    float4 v = *(const float4*)(enc + i);
    __half h[4];
    h[0] = __float2half_rn(v.x);
    h[1] = __float2half_rn(v.y);
    h[2] = __float2half_rn(v.z);
    h[3] = __float2half_rn(v.w);
    *(uint2*)(g_eh + i) = *(uint2*)h;
}

// ---------------- prep: h1 -> fp16 ----------------
__global__ void conv_h1(const float* __restrict__ h1) {
    int i = (blockIdx.x * 256 + threadIdx.x) * 4;
    float4 v = *(const float4*)(h1 + i);
    __half hh[4];
    hh[0] = __float2half_rn(v.x);
    hh[1] = __float2half_rn(v.y);
    hh[2] = __float2half_rn(v.z);
    hh[3] = __float2half_rn(v.w);
    *(uint2*)(g_h1h + i) = *(uint2*)hh;
}

// ---------------- helpers ----------------
__device__ __forceinline__ uint32_t smem_u32(const void* p) {
    uint32_t a;
    asm("{ .reg .u64 t; cvta.to.shared.u64 t, %1; cvt.u32.u64 %0, t; }" : "=r"(a) : "l"(p));
    return a;
}
__device__ __forceinline__ void cp16(void* s, const void* g) {
    asm volatile("cp.async.cg.shared.global [%0], [%1], 16;"
                 :: "r"(smem_u32(s)), "l"(g));
}
__device__ __forceinline__ void cp_commit() {
    asm volatile("cp.async.commit_group;" ::: "memory");
}
template <int N>
__device__ __forceinline__ void cp_wait() {
    asm volatile("cp.async.wait_group %0;" :: "n"(N) : "memory");
}
__device__ __forceinline__ void mma16816(float* d, const uint32_t* a, const uint32_t* b) {
    asm volatile("mma.sync.aligned.m16n8k16.row.col.f32.f16.f16.f32 "
                 "{%0,%1,%2,%3}, {%4,%5,%6,%7}, {%8,%9}, {%0,%1,%2,%3};"
                 : "+f"(d[0]), "+f"(d[1]), "+f"(d[2]), "+f"(d[3])
                 : "r"(a[0]), "r"(a[1]), "r"(a[2]), "r"(a[3]),
                   "r"(b[0]), "r"(b[1]));
}
__device__ __forceinline__ void ldsm4(uint32_t* r, uint32_t addr) {
    asm volatile("ldmatrix.sync.aligned.m8n8.x4.shared.b16 {%0,%1,%2,%3}, [%4];"
                 : "=r"(r[0]), "=r"(r[1]), "=r"(r[2]), "=r"(r[3]) : "r"(addr));
}

// ================= attention GEMM (+ fused w_out conversion in aux blocks) =================
#define ASTRIDE 72
#define MATH (128 * ASTRIDE)
#define STAGE_BYTES (2 * MATH * 2)
#define NSTAGE 4
#define SMEM_TOTAL_ATT (NSTAGE * STAGE_BYTES)
#define KC 64
#define KT (HID / KC)

__global__ void __launch_bounds__(512, 1)
attn_mma(const float* __restrict__ w2, const float* __restrict__ wout) {
    extern __shared__ char smem[];
    const int tid = threadIdx.x;

    // ---- aux blocks: w_out fp32 -> fp16 (grid-stride), fully hidden under attn ----
    if (blockIdx.y >= 512) {
        const int aux = (blockIdx.y - 512) * NCHUNK + blockIdx.x;   // 0..511
        const size_t total4 = (size_t)VOCAB * HID / 4;              // 12,865,792
        for (size_t i = (size_t)aux * 512 + tid; i < total4; i += (size_t)512 * 512) {
            float4 v = *(const float4*)(wout + i * 4);
            __half h[4];
            h[0] = __float2half_rn(v.x);
            h[1] = __float2half_rn(v.y);
            h[2] = __float2half_rn(v.z);
            h[3] = __float2half_rn(v.w);
            *(uint2*)(g_wh + i * 4) = *(uint2*)h;
        }
        return;
    }

    const uint32_t sbase = smem_u32(smem);
    const int bn = blockIdx.x;
    const int mt = blockIdx.y;
    const int wid = tid >> 5, lane = tid & 31;
    const int wm = wid >> 2, wn = wid & 3;
    const int qr = lane >> 2, qc = lane & 3;

    const __half* gAh = g_eh + (size_t)mt * 128 * HID;
    const __half* gBh = g_bh + (size_t)(bn * 128) * HID;

    const int lr = tid >> 2, lc = tid & 3;

    auto issue_load = [&](int kt) {
        char* base = smem + (kt % NSTAGE) * STAGE_BYTES;
        __half* sAh = (__half*)base;
        __half* sBh = sAh + MATH;
        #pragma unroll
        for (int i = 0; i < 2; i++) {
            int c = lc + i * 4;
            size_t go = (size_t)lr * HID + kt * KC + c * 8;
            int so = lr * ASTRIDE + c * 8;
            cp16(sAh + so, gAh + go);
            cp16(sBh + so, gBh + go);
        }
        cp_commit();
    };

    int offA[2];
    #pragma unroll
    for (int m = 0; m < 2; m++)
        offA[m] = ((wm * 32 + m * 16 + (lane & 15)) * ASTRIDE + (lane >> 4) * 8) * 2;
    int offB[2];
    #pragma unroll
    for (int j = 0; j < 2; j++)
        offB[j] = ((wn * 32 + (2 * j + (lane >> 4)) * 8 + (lane & 7)) * ASTRIDE
                   + ((lane >> 3) & 1) * 8) * 2;

    float acc[2][4][4] = {};

    auto compute = [&](int kt) {
        const uint32_t base = sbase + (kt % NSTAGE) * STAGE_BYTES;
        const uint32_t uAh = base;
        const uint32_t uBh = base + MATH * 2;
        #pragma unroll
        for (int ks = 0; ks < KC; ks += 16) {
            uint32_t ah[2][4], bh[4][2];
            #pragma unroll
            for (int m = 0; m < 2; m++)
                ldsm4(ah[m], uAh + offA[m] + ks * 2);
            #pragma unroll
            for (int j = 0; j < 2; j++) {
                uint32_t r[4];
                ldsm4(r, uBh + offB[j] + ks * 2);
                bh[2 * j][0] = r[0]; bh[2 * j][1] = r[1];
                bh[2 * j + 1][0] = r[2]; bh[2 * j + 1][1] = r[3];
            }
            #pragma unroll
            for (int m = 0; m < 2; m++)
                #pragma unroll
                for (int n = 0; n < 4; n++) mma16816(acc[m][n], ah[m], bh[n]);
        }
    };

    issue_load(0);
    issue_load(1);
    issue_load(2);
    for (int kt = 0; kt < KT; kt++) {
        cp_wait<2>();
        __syncthreads();
        if (kt + 3 < KT) issue_load(kt + 3);
        else cp_commit();
        compute(kt);
    }

    float rsum[2][2] = {};
    #pragma unroll
    for (int m = 0; m < 2; m++) {
        #pragma unroll
        for (int n = 0; n < 4; n++) {
            int ng0 = bn * 128 + wn * 32 + n * 8 + qc * 2;
            float w20 = w2[ng0], w21 = w2[ng0 + 1];
            #pragma unroll
            for (int pr = 0; pr < 2; pr++) {
                int row_local = wm * 32 + m * 16 + qr + pr * 8;
                int b = row_local & 63;
                const float* dp = g_dproj + (size_t)b * HID + ng0;
                rsum[m][pr] += tanhf(acc[m][n][pr * 2 + 0] + dp[0]) * w20
                             + tanhf(acc[m][n][pr * 2 + 1] + dp[1]) * w21;
            }
        }
    }
    #pragma unroll
    for (int m = 0; m < 2; m++)
        #pragma unroll
        for (int pr = 0; pr < 2; pr++) {
            float v = rsum[m][pr];
            v += __shfl_xor_sync(0xffffffffu, v, 1);
            v += __shfl_xor_sync(0xffffffffu, v, 2);
            rsum[m][pr] = v;
        }
    float* part = (float*)smem;
    __syncthreads();
    if (qc == 0) {
        #pragma unroll
        for (int m = 0; m < 2; m++)
            #pragma unroll
            for (int pr = 0; pr < 2; pr++)
                part[(wm * 32 + m * 16 + qr + pr * 8) * 4 + wn] = rsum[m][pr];
    }
    __syncthreads();
    if (tid < 128) {
        float e = part[tid * 4 + 0] + part[tid * 4 + 1] + part[tid * 4 + 2] + part[tid * 4 + 3];
        g_epart[(size_t)bn * (MAXLEN * BATCH) + mt * 128 + tid] = e;
    }
}

// ================= logits GEMM: single-pass fp16 A, fp16 B =================
#define L_ASTR 72
#define L_MA (64 * L_ASTR)
#define L_MB (128 * L_ASTR)
#define L_STAGE ((L_MA + L_MB) * 2)
#define L_NSTAGE 4
#define SMEM_TOTAL_LOG (L_NSTAGE * L_STAGE)

__global__ void __launch_bounds__(256, 1)
logits_mma(const float* __restrict__ bias, float* __restrict__ out) {
    extern __shared__ char smem[];
    const uint32_t sbase = smem_u32(smem);
    const int n0 = blockIdx.x * 128;
    const int tid = threadIdx.x;
    const int wid = tid >> 5, lane = tid & 31;
    const int wm = wid >> 2, wn = wid & 3;
    const int qr = lane >> 2, qc = lane & 3;

    const int ar = tid >> 2, ac = tid & 3;
    const int br = tid >> 1, bc0 = (tid & 1) * 4;

    auto issue_load = [&](int kt) {
        char* base = smem + (kt % L_NSTAGE) * L_STAGE;
        __half* sAh = (__half*)base;
        __half* sB  = sAh + L_MA;
        #pragma unroll
        for (int i = 0; i < 2; i++) {
            int c = ac + i * 4;
            size_t go = (size_t)ar * HID + kt * KC + c * 8;
            cp16(sAh + ar * L_ASTR + c * 8, g_h1h + go);
        }
        int gn = n0 + br; if (gn >= VOCAB) gn = VOCAB - 1;
        #pragma unroll
        for (int i = 0; i < 4; i++) {
            int c = bc0 + i;
            cp16(sB + br * L_ASTR + c * 8, g_wh + (size_t)gn * HID + kt * KC + c * 8);
        }
        cp_commit();
    };

    int offA[2];
    #pragma unroll
    for (int m = 0; m < 2; m++)
        offA[m] = ((wm * 32 + m * 16 + (lane & 15)) * L_ASTR + (lane >> 4) * 8) * 2;
    int offB[2];
    #pragma unroll
    for (int j = 0; j < 2; j++)
        offB[j] = ((wn * 32 + (2 * j + (lane >> 4)) * 8 + (lane & 7)) * L_ASTR
                   + ((lane >> 3) & 1) * 8) * 2;

    float acc[2][4][4] = {};

    auto compute = [&](int kt) {
        const uint32_t base = sbase + (kt % L_NSTAGE) * L_STAGE;
        const uint32_t uAh = base;
        const uint32_t uB  = base + L_MA * 2;
        #pragma unroll
        for (int ks = 0; ks < KC; ks += 16) {
            uint32_t ah[2][4], bb[4][2];
            #pragma unroll
            for (int m = 0; m < 2; m++)
                ldsm4(ah[m], uAh + offA[m] + ks * 2);
            #pragma unroll
            for (int j = 0; j < 2; j++) {
                uint32_t r[4];
                ldsm4(r, uB + offB[j] + ks * 2);
                bb[2 * j][0] = r[0]; bb[2 * j][1] = r[1];
                bb[2 * j + 1][0] = r[2]; bb[2 * j + 1][1] = r[3];
            }
            #pragma unroll
            for (int m = 0; m < 2; m++)
                #pragma unroll
                for (int n = 0; n < 4; n++) mma16816(acc[m][n], ah[m], bb[n]);
        }
    };

    issue_load(0);
    issue_load(1);
    issue_load(2);
    for (int kt = 0; kt < KT; kt++) {
        cp_wait<2>();
        __syncthreads();
        if (kt + 3 < KT) issue_load(kt + 3);
        else cp_commit();
        compute(kt);
    }

    #pragma unroll
    for (int m = 0; m < 2; m++) {
        #pragma unroll
        for (int n = 0; n < 4; n++) {
            int col = n0 + wn * 32 + n * 8 + qc * 2;
            #pragma unroll
            for (int pr = 0; pr < 2; pr++) {
                int row = wm * 32 + m * 16 + qr + pr * 8;
                if (col < VOCAB)
                    out[(size_t)row * VOCAB + col] = acc[m][n][pr * 2 + 0] + bias[col];
                if (col + 1 < VOCAB)
                    out[(size_t)row * VOCAB + col + 1] = acc[m][n][pr * 2 + 1] + bias[col + 1];
            }
        }
    }
}

// ---------------- K-split M=64 fp32 GEMM: partials to C[ks][64][ldc] ----------------
template <bool BT>
__global__ void gemm64_ks(const float* __restrict__ A, const float* __restrict__ B,
                          float* __restrict__ C, int N, int K, int ldc) {
    __shared__ float As[64][16];
    __shared__ float Bs[16][64];
    const int nT  = blockIdx.x * 64;
    const int ks  = blockIdx.y;
    const int Kseg = K / KSPL;
    A += ks * Kseg;
    const float* Bp = BT ? (B + ks * Kseg) : (B + (size_t)ks * Kseg * N);
    C += (size_t)ks * 64 * ldc;
    const int tid = threadIdx.x;
    const int tx  = tid & 15, ty = tid >> 4;
    const int m4  = tid >> 2, kq = tid & 3;

    float acc[4][4] = {};
    for (int k0 = 0; k0 < Kseg; k0 += 16) {
        float4 avv = *(const float4*)(A + (size_t)m4 * K + k0 + kq * 4);
        *(float4*)&As[m4][kq * 4] = avv;
        if (BT) {
            int n = tid >> 2;
            int gn = nT + n;
            float4 bv = make_float4(0.f, 0.f, 0.f, 0.f);
            if (gn < N) bv = *(const float4*)(Bp + (size_t)gn * K + k0 + kq * 4);
            Bs[kq * 4 + 0][n] = bv.x;
            Bs[kq * 4 + 1][n] = bv.y;
            Bs[kq * 4 + 2][n] = bv.z;
            Bs[kq * 4 + 3][n] = bv.w;
        } else {
            #pragma unroll
            for (int e2 = 0; e2 < 4; e2++) {
                int lin = tid + e2 * 256;
                int kk = lin >> 6, n = lin & 63;
                int gn = nT + n;
                Bs[kk][n] = (gn < N) ? Bp[(size_t)(k0 + kk) * N + gn] : 0.f;
            }
        }
        __syncthreads();
        #pragma unroll
        for (int kk = 0; kk < 16; kk++) {
            float4 b4 = *(const float4*)&Bs[kk][tx * 4];
            float bj[4] = {b4.x, b4.y, b4.z, b4.w};
            #pragma unroll
            for (int i = 0; i < 4; i++) {
                float a = As[ty * 4 + i][kk];
                #pragma unroll
                for (int j = 0; j < 4; j++) acc[i][j] = fmaf(a, bj[j], acc[i][j]);
            }
        }
        __syncthreads();
    }
    #pragma unroll
    for (int i = 0; i < 4; i++) {
        int m = ty * 4 + i;
        #pragma unroll
        for (int j = 0; j < 4; j++) {
            int n = nT + tx * 4 + j;
            if (n < N) C[(size_t)m * ldc + n] = acc[i][j];
        }
    }
}

// ---------------- reduce dproj partials ----------------
__global__ void reduce_dproj() {
    int i = blockIdx.x * 256 + threadIdx.x;
    float s = 0.f;
    #pragma unroll
    for (int p = 0; p < KSPL; p++) s += g_dp4[p * (BATCH * HID) + i];
    g_dproj[i] = s;
}

// ---------------- softmax over t ----------------
__global__ void softmax_kernel() {
    const int b = blockIdx.x;
    __shared__ float es[MAXLEN];
    __shared__ float red[256];
    const int tid = threadIdx.x;

    float mx = -1e30f;
    for (int t = tid; t < MAXLEN; t += 256) {
        float s = 0.f;
        #pragma unroll
        for (int p = 0; p < NCHUNK; p++) s += g_epart[p * (MAXLEN * BATCH) + t * 64 + b];
        es[t] = s;
        mx = fmaxf(mx, s);
    }
    red[tid] = mx; __syncthreads();
    for (int s2 = 128; s2; s2 >>= 1) {
        if (tid < s2) red[tid] = fmaxf(red[tid], red[tid + s2]);
        __syncthreads();
    }
    mx = red[0]; __syncthreads();

    float sum = 0.f;
    for (int t = tid; t < MAXLEN; t += 256) {
        float v = __expf(es[t] - mx);
        es[t] = v;
        sum += v;
    }
    red[tid] = sum; __syncthreads();
    for (int s2 = 128; s2; s2 >>= 1) {
        if (tid < s2) red[tid] += red[tid + s2];
        __syncthreads();
    }
    float inv = 1.f / red[0];
    for (int t = tid; t < MAXLEN; t += 256) g_alpha[t * 64 + b] = es[t] * inv;
}

// ---------------- context (fp16 enc) ----------------
__global__ void context_kernel() {
    const int b = blockIdx.x, seg = blockIdx.y;
    const int h = threadIdx.x;
    float acc = 0.f;
    #pragma unroll 4
    for (int t = seg * 128; t < (seg + 1) * 128; t++)
        acc = fmaf(g_alpha[t * 64 + b],
                   __half2float(g_eh[((size_t)t * 64 + b) * HID + h]), acc);
    g_cpart[(seg * BATCH + b) * HID + h] = acc;
}

// ---------------- x = concat(embedding[cur], c) ----------------
__global__ void build_x(const int* __restrict__ cur, const float* __restrict__ emb) {
    const int b = blockIdx.x, tid = threadIdx.x;
    const int tok = cur[b];
    for (int k = tid; k < EMBED; k += 512)
        g_x[b * (EMBED + HID) + k] = emb[(size_t)tok * EMBED + k];
    for (int k = tid; k < HID; k += 512) {
        float s = 0.f;
        #pragma unroll
        for (int p = 0; p < 8; p++) s += g_cpart[(p * BATCH + b) * HID + k];
        g_x[b * (EMBED + HID) + EMBED + k] = s;
    }
}

// ---------------- GRU gates (reduces K-split partials, adds biases) ----------------
__global__ void gru_gates(const float* __restrict__ hprev,
                          const float* __restrict__ b_ih,
                          const float* __restrict__ b_hh,
                          float* __restrict__ out1, float* __restrict__ out2) {
    const int idx = blockIdx.x * 256 + threadIdx.x;
    const int b = idx >> 10, q = idx & 1023;
    const int base = b * 3072 + q;
    float ir = b_ih[q], iz = b_ih[q + 1024], in_ = b_ih[q + 2048];
    float hr = b_hh[q], hz = b_hh[q + 1024], hn = b_hh[q + 2048];
    #pragma unroll
    for (int p = 0; p < KSPL; p++) {
        const float* gi = g_gi + p * (BATCH * 3 * HID);
        const float* gh = g_gh + p * (BATCH * 3 * HID);
        ir += gi[base];        hr += gh[base];
        iz += gi[base + 1024]; hz += gh[base + 1024];
        in_ += gi[base + 2048]; hn += gh[base + 2048];
    }
    float r = 1.f / (1.f + __expf(-(ir + hr)));
    float z = 1.f / (1.f + __expf(-(iz + hz)));
    float n = tanhf(in_ + r * hn);
    float h = (1.f - z) * n + z * hprev[idx];
    out1[idx] = h;
    if (out2) out2[idx] = h;
}

// ---------------- launch (single stream; graph-capture safe) ----------------
extern "C" void kernel_launch(void* const* d_in, const int* in_sizes, int n_in,
                              void* d_out, int out_size) {
    const int*   cur    = (const int*)d_in[0];
    const float* state  = (const float*)d_in[1];
    const float* enc    = (const float*)d_in[2];
    const float* emb    = (const float*)d_in[3];
    const float* w_att1 = (const float*)d_in[4];
    const float* w_att2 = (const float*)d_in[5];
    const float* w_ih0  = (const float*)d_in[6];
    const float* w_hh0  = (const float*)d_in[7];
    const float* b_ih0  = (const float*)d_in[8];
    const float* b_hh0  = (const float*)d_in[9];
    const float* w_ih1  = (const float*)d_in[10];
    const float* w_hh1  = (const float*)d_in[11];
    const float* b_ih1  = (const float*)d_in[12];
    const float* b_hh1  = (const float*)d_in[13];
    const float* w_out  = (const float*)d_in[14];
    const float* b_out  = (const float*)d_in[15];

    float* out = (float*)d_out;
    float* st0 = out + (size_t)BATCH * VOCAB;
    float* st1 = st0 + BATCH * HID;

    float *p_dp4, *p_x, *p_gi, *p_gh, *p_h0;
    cudaGetSymbolAddress((void**)&p_dp4, g_dp4);
    cudaGetSymbolAddress((void**)&p_x,   g_x);
    cudaGetSymbolAddress((void**)&p_gi,  g_gi);
    cudaGetSymbolAddress((void**)&p_gh,  g_gh);
    cudaGetSymbolAddress((void**)&p_h0,  g_h0);

    cudaFuncSetAttribute(attn_mma, cudaFuncAttributeMaxDynamicSharedMemorySize,
                         SMEM_TOTAL_ATT);
    cudaFuncSetAttribute(logits_mma, cudaFuncAttributeMaxDynamicSharedMemorySize,
                         SMEM_TOTAL_LOG);

    const float* dec = state + (size_t)BATCH * HID;

    // 0. prep (w_out conversion is fused into attn_mma aux blocks)
    prep_b<<<dim3(32, 32), dim3(32, 8)>>>(w_att1);
    prep_enc<<<(MAXLEN * BATCH * HID) / (256 * 4), 256>>>(enc);
    // 1. dproj = dec @ w1_d  (K-split + reduce)
    gemm64_ks<false><<<dim3(16, KSPL), 256>>>(dec, w_att1 + (size_t)HID * HID,
                                              p_dp4, HID, HID, HID);
    reduce_dproj<<<BATCH * HID / 256, 256>>>();
    // 2. attention energies (+ fused w_out->fp16 aux blocks)
    attn_mma<<<dim3(NCHUNK, 512 + AUXY), 512, SMEM_TOTAL_ATT>>>(w_att2, w_out);
    // 3. softmax
    softmax_kernel<<<BATCH, 256>>>();
    // 4. context (fp16 enc)
    context_kernel<<<dim3(BATCH, 8), 1024>>>();
    // 5. x = concat(emb, c)
    build_x<<<BATCH, 512>>>(cur, emb);
    // 6. GRU layer 0
    gemm64_ks<true><<<dim3(48, KSPL), 256>>>(p_x,   w_ih0, p_gi, 3 * HID, EMBED + HID, 3 * HID);
    gemm64_ks<true><<<dim3(48, KSPL), 256>>>(state, w_hh0, p_gh, 3 * HID, HID,         3 * HID);
    gru_gates<<<256, 256>>>(state, b_ih0, b_hh0, st0, p_h0);
    // 7. GRU layer 1
    gemm64_ks<true><<<dim3(48, KSPL), 256>>>(p_h0, w_ih1, p_gi, 3 * HID, HID, 3 * HID);
    gemm64_ks<true><<<dim3(48, KSPL), 256>>>(dec,  w_hh1, p_gh, 3 * HID, HID, 3 * HID);
    gru_gates<<<256, 256>>>(dec, b_ih1, b_hh1, st1, nullptr);
    // 8. logits: single-pass fp16 tensor GEMM
    conv_h1<<<BATCH, 256>>>(st1);
    logits_mma<<<(VOCAB + 127) / 128, 256, SMEM_TOTAL_LOG>>>(b_out, out);
}